// round 1
// baseline (speedup 1.0000x reference)
#include <cuda_runtime.h>
#include <cstdint>

#define L_FACES 8192
#define S_EDGES 8192
#define EDIM    256
#define MAXLOOP 16

// Scratch (no allocation allowed in kernel_launch)
__device__ float g_Q   [L_FACES * EDIM];
__device__ float g_KV  [S_EDGES * 512];     // cols 0..255 = K, 256..511 = V
__device__ float g_attn[L_FACES * EDIM];
__device__ float g_proj[L_FACES * EDIM];
__device__ float g_x   [L_FACES * EDIM];

// ---------------------------------------------------------------------------
// GEMM: C[M,N] = A[M,256] * B[N,256]^T + bias[N]; A,B row-major, K=256.
// 128x128 block tile, BK=16, 256 threads, 8x8 per-thread register tile.
// ---------------------------------------------------------------------------
__global__ __launch_bounds__(256, 2)
void gemm_nt_bias(const float* __restrict__ A, const float* __restrict__ B,
                  const float* __restrict__ bias, float* __restrict__ C, int ldc)
{
    constexpr int K = 256, BM = 128, BN = 128, BK = 16;
    __shared__ float As[BK][BM];
    __shared__ float Bs[BK][BN];

    const int tid = threadIdx.x;
    const int m0  = blockIdx.x * BM;
    const int n0  = blockIdx.y * BN;

    const int loadRow = tid >> 2;          // 0..63
    const int loadCol = (tid & 3) << 2;    // 0,4,8,12
    const float* Ag = A + (size_t)(m0 + loadRow) * K + loadCol;
    const float* Bg = B + (size_t)(n0 + loadRow) * K + loadCol;

    const int tRow = (tid >> 4) << 3;      // 0..120
    const int tCol = (tid & 15) << 3;      // 0..120

    float acc[8][8];
#pragma unroll
    for (int i = 0; i < 8; ++i)
#pragma unroll
        for (int j = 0; j < 8; ++j) acc[i][j] = 0.f;

    for (int k0 = 0; k0 < K; k0 += BK) {
#pragma unroll
        for (int r = 0; r < 2; ++r) {
            float4 a = *(const float4*)(Ag + (size_t)(r * 64) * K + k0);
            float4 b = *(const float4*)(Bg + (size_t)(r * 64) * K + k0);
            As[loadCol + 0][loadRow + r * 64] = a.x;
            As[loadCol + 1][loadRow + r * 64] = a.y;
            As[loadCol + 2][loadRow + r * 64] = a.z;
            As[loadCol + 3][loadRow + r * 64] = a.w;
            Bs[loadCol + 0][loadRow + r * 64] = b.x;
            Bs[loadCol + 1][loadRow + r * 64] = b.y;
            Bs[loadCol + 2][loadRow + r * 64] = b.z;
            Bs[loadCol + 3][loadRow + r * 64] = b.w;
        }
        __syncthreads();
#pragma unroll
        for (int kk = 0; kk < BK; ++kk) {
            float rm[8], rn[8];
            *(float4*)&rm[0] = *(const float4*)&As[kk][tRow];
            *(float4*)&rm[4] = *(const float4*)&As[kk][tRow + 4];
            *(float4*)&rn[0] = *(const float4*)&Bs[kk][tCol];
            *(float4*)&rn[4] = *(const float4*)&Bs[kk][tCol + 4];
#pragma unroll
            for (int i = 0; i < 8; ++i)
#pragma unroll
                for (int j = 0; j < 8; ++j)
                    acc[i][j] = fmaf(rm[i], rn[j], acc[i][j]);
        }
        __syncthreads();
    }

    float bv[8];
#pragma unroll
    for (int j = 0; j < 8; ++j) bv[j] = bias[n0 + tCol + j];
#pragma unroll
    for (int i = 0; i < 8; ++i) {
        float* cp = C + (size_t)(m0 + tRow + i) * ldc + n0 + tCol;
        *(float4*)cp       = make_float4(acc[i][0] + bv[0], acc[i][1] + bv[1],
                                         acc[i][2] + bv[2], acc[i][3] + bv[3]);
        *(float4*)(cp + 4) = make_float4(acc[i][4] + bv[4], acc[i][5] + bv[5],
                                         acc[i][6] + bv[6], acc[i][7] + bv[7]);
    }
}

// ---------------------------------------------------------------------------
// Attention: one warp per face. ≤16 edge indices, dedup (mask semantics),
// per-head (H=2, DH=128) softmax over valid unique edges, weighted V sum.
// Lane owns 8 contiguous dims of E=256; lanes 0-15 = head0, 16-31 = head1.
// ---------------------------------------------------------------------------
__global__ __launch_bounds__(256)
void attn_kernel(const int* __restrict__ loop, const float* __restrict__ Q,
                 const float* __restrict__ KV, float* __restrict__ out)
{
    const int warp = threadIdx.x >> 5;
    const int lane = threadIdx.x & 31;
    const int face = (blockIdx.x << 3) + warp;

    __shared__ int sidx[8][16];
    if (lane < 16) sidx[warp][lane] = loop[face * MAXLOOP + lane];
    __syncwarp();

    // validity + dedup (keep first occurrence; -1/-2 invalid)
    bool v = false;
    if (lane < 16) {
        const int my = sidx[warp][lane];
        v = (my >= 0);
        for (int j = 0; v && j < lane; ++j)
            if (sidx[warp][j] == my) v = false;
    }
    const unsigned bal = __ballot_sync(0xffffffffu, v);   // bits 0..15

    const float scale = 0.08838834764831845f;             // 1/sqrt(128)
    const float* qp = Q + (size_t)face * EDIM + lane * 8;
    float4 q0 = *(const float4*)qp;
    float4 q1 = *(const float4*)(qp + 4);
    q0.x *= scale; q0.y *= scale; q0.z *= scale; q0.w *= scale;
    q1.x *= scale; q1.y *= scale; q1.z *= scale; q1.w *= scale;

    float myscore = -3e38f;
#pragma unroll
    for (int i = 0; i < 16; ++i) {
        if (!(bal & (1u << i))) continue;                 // uniform across warp
        const int idx = sidx[warp][i];
        const float* kp = KV + (size_t)idx * 512 + lane * 8;
        float4 k0 = *(const float4*)kp;
        float4 k1 = *(const float4*)(kp + 4);
        float p = q0.x * k0.x + q0.y * k0.y + q0.z * k0.z + q0.w * k0.w
                + q1.x * k1.x + q1.y * k1.y + q1.z * k1.z + q1.w * k1.w;
        p += __shfl_xor_sync(0xffffffffu, p, 8);          // reduce within 16-lane head group
        p += __shfl_xor_sync(0xffffffffu, p, 4);
        p += __shfl_xor_sync(0xffffffffu, p, 2);
        p += __shfl_xor_sync(0xffffffffu, p, 1);
        if ((lane & 15) == i) myscore = p;                // lane i: head0, lane 16+i: head1
    }

    const bool mv = (bal >> (lane & 15)) & 1u;
    float s = mv ? myscore : -3e38f;
    float mx = s;
#pragma unroll
    for (int d = 8; d; d >>= 1) mx = fmaxf(mx, __shfl_xor_sync(0xffffffffu, mx, d));
    float e = mv ? __expf(s - mx) : 0.f;
    float sum = e;
#pragma unroll
    for (int d = 8; d; d >>= 1) sum += __shfl_xor_sync(0xffffffffu, sum, d);
    const float w = e / sum;

    float a0=0.f,a1=0.f,a2=0.f,a3=0.f,a4=0.f,a5=0.f,a6=0.f,a7=0.f;
    const int hb = lane & 16;
#pragma unroll
    for (int i = 0; i < 16; ++i) {
        if (!(bal & (1u << i))) continue;
        const int idx = sidx[warp][i];
        const float wi = __shfl_sync(0xffffffffu, w, hb | i);
        const float* vp = KV + (size_t)idx * 512 + 256 + lane * 8;
        float4 v0 = *(const float4*)vp;
        float4 v1 = *(const float4*)(vp + 4);
        a0 = fmaf(wi, v0.x, a0); a1 = fmaf(wi, v0.y, a1);
        a2 = fmaf(wi, v0.z, a2); a3 = fmaf(wi, v0.w, a3);
        a4 = fmaf(wi, v1.x, a4); a5 = fmaf(wi, v1.y, a5);
        a6 = fmaf(wi, v1.z, a6); a7 = fmaf(wi, v1.w, a7);
    }
    float* op = out + (size_t)face * EDIM + lane * 8;
    *(float4*)op       = make_float4(a0, a1, a2, a3);
    *(float4*)(op + 4) = make_float4(a4, a5, a6, a7);
}

// ---------------------------------------------------------------------------
// out = LayerNorm(x + y) * g + b ; one warp per 256-wide row.
// ---------------------------------------------------------------------------
__global__ __launch_bounds__(256)
void resid_ln(const float* __restrict__ x, const float* __restrict__ y,
              const float* __restrict__ g, const float* __restrict__ b,
              float* __restrict__ out)
{
    const int warp = threadIdx.x >> 5;
    const int lane = threadIdx.x & 31;
    const int row  = (blockIdx.x << 3) + warp;

    const float* xp = x + (size_t)row * EDIM + lane * 8;
    const float* yp = y + (size_t)row * EDIM + lane * 8;
    float4 x0 = *(const float4*)xp, x1 = *(const float4*)(xp + 4);
    float4 y0 = *(const float4*)yp, y1 = *(const float4*)(yp + 4);
    float v[8] = { x0.x + y0.x, x0.y + y0.y, x0.z + y0.z, x0.w + y0.w,
                   x1.x + y1.x, x1.y + y1.y, x1.z + y1.z, x1.w + y1.w };

    float s = 0.f;
#pragma unroll
    for (int j = 0; j < 8; ++j) s += v[j];
#pragma unroll
    for (int d = 16; d; d >>= 1) s += __shfl_xor_sync(0xffffffffu, s, d);
    const float m = s * (1.f / 256.f);

    float ss = 0.f;
#pragma unroll
    for (int j = 0; j < 8; ++j) { const float dd = v[j] - m; ss += dd * dd; }
#pragma unroll
    for (int d = 16; d; d >>= 1) ss += __shfl_xor_sync(0xffffffffu, ss, d);
    const float inv = rsqrtf(ss * (1.f / 256.f) + 1e-5f);

    const float4 g0 = *(const float4*)(g + lane * 8);
    const float4 g1 = *(const float4*)(g + lane * 8 + 4);
    const float4 b0 = *(const float4*)(b + lane * 8);
    const float4 b1 = *(const float4*)(b + lane * 8 + 4);

    float* op = out + (size_t)row * EDIM + lane * 8;
    *(float4*)op = make_float4((v[0] - m) * inv * g0.x + b0.x,
                               (v[1] - m) * inv * g0.y + b0.y,
                               (v[2] - m) * inv * g0.z + b0.z,
                               (v[3] - m) * inv * g0.w + b0.w);
    *(float4*)(op + 4) = make_float4((v[4] - m) * inv * g1.x + b1.x,
                                     (v[5] - m) * inv * g1.y + b1.y,
                                     (v[6] - m) * inv * g1.z + b1.z,
                                     (v[7] - m) * inv * g1.w + b1.w);
}

// ---------------------------------------------------------------------------
extern "C" void kernel_launch(void* const* d_in, const int* in_sizes, int n_in,
                              void* d_out, int out_size)
{
    const int*   loop  = (const int*)  d_in[0];
    // d_in[1] = v_face_mask (all true) — unused
    const float* edge  = (const float*)d_in[2];
    const float* face  = (const float*)d_in[3];
    const float* w_in1  = (const float*)d_in[4];
    const float* b_in1  = (const float*)d_in[5];
    const float* w_out1 = (const float*)d_in[6];
    const float* b_out1 = (const float*)d_in[7];
    const float* ln1_g  = (const float*)d_in[8];
    const float* ln1_b  = (const float*)d_in[9];
    const float* w_in2  = (const float*)d_in[10];
    const float* b_in2  = (const float*)d_in[11];
    const float* w_out2 = (const float*)d_in[12];
    const float* b_out2 = (const float*)d_in[13];
    const float* ln2_g  = (const float*)d_in[14];
    const float* ln2_b  = (const float*)d_in[15];

    float *Q, *KV, *ATT, *PR, *X;
    cudaGetSymbolAddress((void**)&Q,   g_Q);
    cudaGetSymbolAddress((void**)&KV,  g_KV);
    cudaGetSymbolAddress((void**)&ATT, g_attn);
    cudaGetSymbolAddress((void**)&PR,  g_proj);
    cudaGetSymbolAddress((void**)&X,   g_x);

    const dim3 blk(256);
    const dim3 gQ(64, 2), gKV(64, 4), gO(64, 2);

    // ---- layer 1 ----
    gemm_nt_bias<<<gQ,  blk>>>(face, w_in1,             b_in1,       Q,  256);
    gemm_nt_bias<<<gKV, blk>>>(edge, w_in1 + 256 * 256, b_in1 + 256, KV, 512);
    attn_kernel <<<1024, blk>>>(loop, Q, KV, ATT);
    gemm_nt_bias<<<gO,  blk>>>(ATT, w_out1, b_out1, PR, 256);
    resid_ln    <<<1024, blk>>>(face, PR, ln1_g, ln1_b, X);

    // ---- layer 2 ----
    gemm_nt_bias<<<gQ,  blk>>>(X,    w_in2,             b_in2,       Q,  256);
    gemm_nt_bias<<<gKV, blk>>>(edge, w_in2 + 256 * 256, b_in2 + 256, KV, 512);
    attn_kernel <<<1024, blk>>>(loop, Q, KV, ATT);
    gemm_nt_bias<<<gO,  blk>>>(ATT, w_out2, b_out2, PR, 256);
    resid_ln    <<<1024, blk>>>(X, PR, ln2_g, ln2_b, (float*)d_out);
}

// round 2
// speedup vs baseline: 1.0613x; 1.0613x over previous
#include <cuda_runtime.h>
#include <cstdint>

#define L_FACES 8192
#define S_EDGES 8192
#define EDIM    256
#define MAXLOOP 16

typedef unsigned long long u64;

// Scratch (no allocation allowed in kernel_launch)
__device__ float g_Q   [L_FACES * EDIM];
__device__ float g_KV  [S_EDGES * 512];     // cols 0..255 = K, 256..511 = V
__device__ float g_attn[L_FACES * EDIM];
__device__ float g_x   [L_FACES * EDIM];

// ---- packed f32x2 helpers -------------------------------------------------
__device__ __forceinline__ u64 pk2(float x, float y) {
    u64 r; asm("mov.b64 %0, {%1, %2};" : "=l"(r) : "f"(x), "f"(y)); return r;
}
__device__ __forceinline__ float2 upk2(u64 v) {
    float2 f; asm("mov.b64 {%0, %1}, %2;" : "=f"(f.x), "=f"(f.y) : "l"(v)); return f;
}
#define FMA2(acc, a, b) \
    asm("fma.rn.f32x2 %0, %1, %2, %0;" : "+l"(acc) : "l"(a), "l"(b))

// ---------------------------------------------------------------------------
// Fused QKV GEMM. One launch:
//   blocks [0,128):   Q  = Aq @ W[0:256]^T   + bias[0:256]    -> Q  (ldc 256)
//   blocks [128,384): KV = Akv @ W[256:768]^T + bias[256:768] -> KV (ldc 512)
// 128x128 tile, BK=16, 256 threads, 8x8/thread via fma.rn.f32x2.
// ---------------------------------------------------------------------------
__global__ __launch_bounds__(256, 2)
void qkv_gemm(const float* __restrict__ Aq, const float* __restrict__ Akv,
              const float* __restrict__ W,  const float* __restrict__ bias,
              float* __restrict__ Qo, float* __restrict__ KVo)
{
    constexpr int K = 256;
    __shared__ float As[16][128];
    __shared__ float Bs[16][128];

    const int bid = blockIdx.x;
    const float *A, *B, *bv; float* C; int ldc, m0, n0;
    if (bid < 128) {
        m0 = (bid & 63) * 128; n0 = (bid >> 6) * 128;
        A = Aq; B = W; bv = bias; C = Qo; ldc = 256;
    } else {
        const int b2 = bid - 128;
        m0 = (b2 & 63) * 128; n0 = (b2 >> 6) * 128;
        A = Akv; B = W + 256 * 256; bv = bias + 256; C = KVo; ldc = 512;
    }

    const int tid = threadIdx.x;
    const int loadRow = tid >> 2;          // 0..63
    const int loadCol = (tid & 3) << 2;    // 0,4,8,12
    const float* Ag = A + (size_t)(m0 + loadRow) * K + loadCol;
    const float* Bg = B + (size_t)(n0 + loadRow) * K + loadCol;

    const int tRow = (tid >> 4) << 3;
    const int tCol = (tid & 15) << 3;

    u64 acc[8][4];
#pragma unroll
    for (int i = 0; i < 8; ++i)
#pragma unroll
        for (int p = 0; p < 4; ++p) acc[i][p] = 0ull;

    for (int k0 = 0; k0 < K; k0 += 16) {
#pragma unroll
        for (int r = 0; r < 2; ++r) {
            float4 a = *(const float4*)(Ag + (size_t)(r * 64) * K + k0);
            float4 b = *(const float4*)(Bg + (size_t)(r * 64) * K + k0);
            As[loadCol + 0][loadRow + r * 64] = a.x;
            As[loadCol + 1][loadRow + r * 64] = a.y;
            As[loadCol + 2][loadRow + r * 64] = a.z;
            As[loadCol + 3][loadRow + r * 64] = a.w;
            Bs[loadCol + 0][loadRow + r * 64] = b.x;
            Bs[loadCol + 1][loadRow + r * 64] = b.y;
            Bs[loadCol + 2][loadRow + r * 64] = b.z;
            Bs[loadCol + 3][loadRow + r * 64] = b.w;
        }
        __syncthreads();
#pragma unroll
        for (int kk = 0; kk < 16; ++kk) {
            float4 rm0 = *(const float4*)&As[kk][tRow];
            float4 rm1 = *(const float4*)&As[kk][tRow + 4];
            const ulonglong2* bp = (const ulonglong2*)&Bs[kk][tCol];
            const ulonglong2 rnA = bp[0];
            const ulonglong2 rnB = bp[1];
            u64 rm2[8];
            rm2[0] = pk2(rm0.x, rm0.x); rm2[1] = pk2(rm0.y, rm0.y);
            rm2[2] = pk2(rm0.z, rm0.z); rm2[3] = pk2(rm0.w, rm0.w);
            rm2[4] = pk2(rm1.x, rm1.x); rm2[5] = pk2(rm1.y, rm1.y);
            rm2[6] = pk2(rm1.z, rm1.z); rm2[7] = pk2(rm1.w, rm1.w);
#pragma unroll
            for (int i = 0; i < 8; ++i) {
                FMA2(acc[i][0], rm2[i], rnA.x);
                FMA2(acc[i][1], rm2[i], rnA.y);
                FMA2(acc[i][2], rm2[i], rnB.x);
                FMA2(acc[i][3], rm2[i], rnB.y);
            }
        }
        __syncthreads();
    }

    float bvv[8];
#pragma unroll
    for (int j = 0; j < 8; ++j) bvv[j] = bv[n0 + tCol + j];
#pragma unroll
    for (int i = 0; i < 8; ++i) {
        float2 c0 = upk2(acc[i][0]), c1 = upk2(acc[i][1]);
        float2 c2 = upk2(acc[i][2]), c3 = upk2(acc[i][3]);
        float* cp = C + (size_t)(m0 + tRow + i) * ldc + n0 + tCol;
        *(float4*)cp       = make_float4(c0.x + bvv[0], c0.y + bvv[1],
                                         c1.x + bvv[2], c1.y + bvv[3]);
        *(float4*)(cp + 4) = make_float4(c2.x + bvv[4], c2.y + bvv[5],
                                         c3.x + bvv[6], c3.y + bvv[7]);
    }
}

// ---------------------------------------------------------------------------
// Fused out-projection + residual + LayerNorm.
// out = LN(resid + A @ W^T + bias) * g + b
// BM=64, BN=256 (full row per block), BK=16, 256 threads, 8x8/thread.
// Warp w owns rows w*8..w*8+7 across all 256 cols -> warp-level LN.
// ---------------------------------------------------------------------------
__global__ __launch_bounds__(256, 2)
void out_ln_gemm(const float* __restrict__ A, const float* __restrict__ W,
                 const float* __restrict__ bias, const float* __restrict__ resid,
                 const float* __restrict__ gg, const float* __restrict__ bb,
                 float* __restrict__ out)
{
    constexpr int K = 256;
    __shared__ float As[16][64];
    __shared__ float Bs[16][256];

    const int tid = threadIdx.x;
    const int m0  = blockIdx.x * 64;

    const int aRow = tid >> 2;             // 0..63
    const int aCol = (tid & 3) << 2;       // 0,4,8,12
    const float* Ag = A + (size_t)(m0 + aRow) * K + aCol;
    const float* Bg = W + (size_t)aRow * K + aCol;

    const int lane = tid & 31, warp = tid >> 5;
    const int tRow = warp * 8;
    const int tCol = lane * 8;

    u64 acc[8][4];
#pragma unroll
    for (int i = 0; i < 8; ++i)
#pragma unroll
        for (int p = 0; p < 4; ++p) acc[i][p] = 0ull;

    for (int k0 = 0; k0 < K; k0 += 16) {
        {
            float4 a = *(const float4*)(Ag + k0);
            As[aCol + 0][aRow] = a.x;
            As[aCol + 1][aRow] = a.y;
            As[aCol + 2][aRow] = a.z;
            As[aCol + 3][aRow] = a.w;
#pragma unroll
            for (int r = 0; r < 4; ++r) {
                float4 b = *(const float4*)(Bg + (size_t)(r * 64) * K + k0);
                Bs[aCol + 0][aRow + r * 64] = b.x;
                Bs[aCol + 1][aRow + r * 64] = b.y;
                Bs[aCol + 2][aRow + r * 64] = b.z;
                Bs[aCol + 3][aRow + r * 64] = b.w;
            }
        }
        __syncthreads();
#pragma unroll
        for (int kk = 0; kk < 16; ++kk) {
            float4 rm0 = *(const float4*)&As[kk][tRow];
            float4 rm1 = *(const float4*)&As[kk][tRow + 4];
            const ulonglong2* bp = (const ulonglong2*)&Bs[kk][tCol];
            const ulonglong2 rnA = bp[0];
            const ulonglong2 rnB = bp[1];
            u64 rm2[8];
            rm2[0] = pk2(rm0.x, rm0.x); rm2[1] = pk2(rm0.y, rm0.y);
            rm2[2] = pk2(rm0.z, rm0.z); rm2[3] = pk2(rm0.w, rm0.w);
            rm2[4] = pk2(rm1.x, rm1.x); rm2[5] = pk2(rm1.y, rm1.y);
            rm2[6] = pk2(rm1.z, rm1.z); rm2[7] = pk2(rm1.w, rm1.w);
#pragma unroll
            for (int i = 0; i < 8; ++i) {
                FMA2(acc[i][0], rm2[i], rnA.x);
                FMA2(acc[i][1], rm2[i], rnA.y);
                FMA2(acc[i][2], rm2[i], rnB.x);
                FMA2(acc[i][3], rm2[i], rnB.y);
            }
        }
        __syncthreads();
    }

    // epilogue: bias + residual + LayerNorm per row (warp-collective)
    float bvv[8], gv[8], bv2[8];
#pragma unroll
    for (int j = 0; j < 8; ++j) {
        bvv[j] = bias[tCol + j];
        gv[j]  = gg[tCol + j];
        bv2[j] = bb[tCol + j];
    }

#pragma unroll
    for (int i = 0; i < 8; ++i) {
        const int row = m0 + tRow + i;
        const float* rp = resid + (size_t)row * EDIM + tCol;
        float4 r0 = *(const float4*)rp;
        float4 r1 = *(const float4*)(rp + 4);
        float2 c0 = upk2(acc[i][0]), c1 = upk2(acc[i][1]);
        float2 c2 = upk2(acc[i][2]), c3 = upk2(acc[i][3]);
        float v[8] = { c0.x + bvv[0] + r0.x, c0.y + bvv[1] + r0.y,
                       c1.x + bvv[2] + r0.z, c1.y + bvv[3] + r0.w,
                       c2.x + bvv[4] + r1.x, c2.y + bvv[5] + r1.y,
                       c3.x + bvv[6] + r1.z, c3.y + bvv[7] + r1.w };
        float s = 0.f, ss = 0.f;
#pragma unroll
        for (int j = 0; j < 8; ++j) { s += v[j]; ss += v[j] * v[j]; }
#pragma unroll
        for (int d = 16; d; d >>= 1) {
            s  += __shfl_xor_sync(0xffffffffu, s,  d);
            ss += __shfl_xor_sync(0xffffffffu, ss, d);
        }
        const float m   = s * (1.f / 256.f);
        const float var = ss * (1.f / 256.f) - m * m;
        const float inv = rsqrtf(var + 1e-5f);

        float* op = out + (size_t)row * EDIM + tCol;
        *(float4*)op = make_float4((v[0] - m) * inv * gv[0] + bv2[0],
                                   (v[1] - m) * inv * gv[1] + bv2[1],
                                   (v[2] - m) * inv * gv[2] + bv2[2],
                                   (v[3] - m) * inv * gv[3] + bv2[3]);
        *(float4*)(op + 4) = make_float4((v[4] - m) * inv * gv[4] + bv2[4],
                                         (v[5] - m) * inv * gv[5] + bv2[5],
                                         (v[6] - m) * inv * gv[6] + bv2[6],
                                         (v[7] - m) * inv * gv[7] + bv2[7]);
    }
}

// ---------------------------------------------------------------------------
// Attention: one warp per face. ≤16 edge indices, dedup, per-head (H=2,
// DH=128) softmax over valid unique edges, weighted V sum.
// ---------------------------------------------------------------------------
__global__ __launch_bounds__(256)
void attn_kernel(const int* __restrict__ loop, const float* __restrict__ Q,
                 const float* __restrict__ KV, float* __restrict__ out)
{
    const int warp = threadIdx.x >> 5;
    const int lane = threadIdx.x & 31;
    const int face = (blockIdx.x << 3) + warp;

    __shared__ int sidx[8][16];
    if (lane < 16) sidx[warp][lane] = loop[face * MAXLOOP + lane];
    __syncwarp();

    bool v = false;
    if (lane < 16) {
        const int my = sidx[warp][lane];
        v = (my >= 0);
        for (int j = 0; v && j < lane; ++j)
            if (sidx[warp][j] == my) v = false;
    }
    const unsigned bal = __ballot_sync(0xffffffffu, v);

    const float scale = 0.08838834764831845f;  // 1/sqrt(128)
    const float* qp = Q + (size_t)face * EDIM + lane * 8;
    float4 q0 = *(const float4*)qp;
    float4 q1 = *(const float4*)(qp + 4);
    q0.x *= scale; q0.y *= scale; q0.z *= scale; q0.w *= scale;
    q1.x *= scale; q1.y *= scale; q1.z *= scale; q1.w *= scale;

    float myscore = -3e38f;
#pragma unroll
    for (int i = 0; i < 16; ++i) {
        if (!(bal & (1u << i))) continue;
        const int idx = sidx[warp][i];
        const float* kp = KV + (size_t)idx * 512 + lane * 8;
        float4 k0 = *(const float4*)kp;
        float4 k1 = *(const float4*)(kp + 4);
        float p = q0.x * k0.x + q0.y * k0.y + q0.z * k0.z + q0.w * k0.w
                + q1.x * k1.x + q1.y * k1.y + q1.z * k1.z + q1.w * k1.w;
        p += __shfl_xor_sync(0xffffffffu, p, 8);
        p += __shfl_xor_sync(0xffffffffu, p, 4);
        p += __shfl_xor_sync(0xffffffffu, p, 2);
        p += __shfl_xor_sync(0xffffffffu, p, 1);
        if ((lane & 15) == i) myscore = p;
    }

    const bool mv = (bal >> (lane & 15)) & 1u;
    float s = mv ? myscore : -3e38f;
    float mx = s;
#pragma unroll
    for (int d = 8; d; d >>= 1) mx = fmaxf(mx, __shfl_xor_sync(0xffffffffu, mx, d));
    float e = mv ? __expf(s - mx) : 0.f;
    float sum = e;
#pragma unroll
    for (int d = 8; d; d >>= 1) sum += __shfl_xor_sync(0xffffffffu, sum, d);
    const float w = e / sum;

    float a0=0.f,a1=0.f,a2=0.f,a3=0.f,a4=0.f,a5=0.f,a6=0.f,a7=0.f;
    const int hb = lane & 16;
#pragma unroll
    for (int i = 0; i < 16; ++i) {
        if (!(bal & (1u << i))) continue;
        const int idx = sidx[warp][i];
        const float wi = __shfl_sync(0xffffffffu, w, hb | i);
        const float* vp = KV + (size_t)idx * 512 + 256 + lane * 8;
        float4 v0 = *(const float4*)vp;
        float4 v1 = *(const float4*)(vp + 4);
        a0 = fmaf(wi, v0.x, a0); a1 = fmaf(wi, v0.y, a1);
        a2 = fmaf(wi, v0.z, a2); a3 = fmaf(wi, v0.w, a3);
        a4 = fmaf(wi, v1.x, a4); a5 = fmaf(wi, v1.y, a5);
        a6 = fmaf(wi, v1.z, a6); a7 = fmaf(wi, v1.w, a7);
    }
    float* op = out + (size_t)face * EDIM + lane * 8;
    *(float4*)op       = make_float4(a0, a1, a2, a3);
    *(float4*)(op + 4) = make_float4(a4, a5, a6, a7);
}

// ---------------------------------------------------------------------------
extern "C" void kernel_launch(void* const* d_in, const int* in_sizes, int n_in,
                              void* d_out, int out_size)
{
    const int*   loop  = (const int*)  d_in[0];
    const float* edge  = (const float*)d_in[2];
    const float* face  = (const float*)d_in[3];
    const float* w_in1  = (const float*)d_in[4];
    const float* b_in1  = (const float*)d_in[5];
    const float* w_out1 = (const float*)d_in[6];
    const float* b_out1 = (const float*)d_in[7];
    const float* ln1_g  = (const float*)d_in[8];
    const float* ln1_b  = (const float*)d_in[9];
    const float* w_in2  = (const float*)d_in[10];
    const float* b_in2  = (const float*)d_in[11];
    const float* w_out2 = (const float*)d_in[12];
    const float* b_out2 = (const float*)d_in[13];
    const float* ln2_g  = (const float*)d_in[14];
    const float* ln2_b  = (const float*)d_in[15];

    float *Q, *KV, *ATT, *X;
    cudaGetSymbolAddress((void**)&Q,   g_Q);
    cudaGetSymbolAddress((void**)&KV,  g_KV);
    cudaGetSymbolAddress((void**)&ATT, g_attn);
    cudaGetSymbolAddress((void**)&X,   g_x);

    // ---- layer 1 ----
    qkv_gemm   <<<384, 256>>>(face, edge, w_in1, b_in1, Q, KV);
    attn_kernel<<<1024, 256>>>(loop, Q, KV, ATT);
    out_ln_gemm<<<128, 256>>>(ATT, w_out1, b_out1, face, ln1_g, ln1_b, X);

    // ---- layer 2 ----
    qkv_gemm   <<<384, 256>>>(X, edge, w_in2, b_in2, Q, KV);
    attn_kernel<<<1024, 256>>>(loop, Q, KV, ATT);
    out_ln_gemm<<<128, 256>>>(ATT, w_out2, b_out2, X, ln2_g, ln2_b, (float*)d_out);
}

// round 4
// speedup vs baseline: 2.0524x; 1.9338x over previous
#include <cuda_runtime.h>
#include <cuda_bf16.h>
#include <cstdint>

typedef unsigned int u32;
typedef unsigned long long u64;
typedef __nv_bfloat16 bf16;

#define EDIM    256
#define MAXLOOP 16

// ---------------------------------------------------------------------------
// Global scratch (no allocation allowed)
// ---------------------------------------------------------------------------
__device__ float g_Q [8192 * 256];
__device__ float g_KV[8192 * 512];          // cols 0..255 = K, 256..511 = V
__device__ float g_X [8192 * 256];
__device__ bf16  g_Ac  [8192 * 512];        // activations hi|lo (face, then X)
__device__ bf16  g_Ec  [8192 * 512];        // edges hi|lo
__device__ bf16  g_ATTc[8192 * 512];        // attention out hi|lo
__device__ bf16  g_Wc1[768 * 512];
__device__ bf16  g_Wc2[768 * 512];
__device__ bf16  g_Wo1[256 * 512];
__device__ bf16  g_Wo2[256 * 512];

// ---------------------------------------------------------------------------
// PTX helpers (all plain sm_80+ features; safe for compute_103 lowering)
// ---------------------------------------------------------------------------
__device__ __forceinline__ u32 smem_u32(const void* p) {
    u32 a; asm("{ .reg .u64 t; cvta.to.shared.u64 t, %1; cvt.u32.u64 %0, t; }"
               : "=r"(a) : "l"(p));
    return a;
}
__device__ __forceinline__ void cpa16(u32 d, const void* s) {
    asm volatile("cp.async.ca.shared.global [%0], [%1], 16;" :: "r"(d), "l"(s));
}
#define CP_COMMIT() asm volatile("cp.async.commit_group;" ::: "memory")
#define CP_WAIT(n)  asm volatile("cp.async.wait_group %0;" :: "n"(n) : "memory")
#define LDSM4(r0, r1, r2, r3, a) \
    asm volatile("ldmatrix.sync.aligned.m8n8.x4.shared.b16 {%0,%1,%2,%3}, [%4];" \
                 : "=r"(r0), "=r"(r1), "=r"(r2), "=r"(r3) : "r"(a))

__device__ __forceinline__ void mma_bf16(float* d, const u32* a, const u32* b) {
    asm volatile("mma.sync.aligned.m16n8k16.row.col.f32.bf16.bf16.f32 "
                 "{%0,%1,%2,%3}, {%4,%5,%6,%7}, {%8,%9}, {%0,%1,%2,%3};"
                 : "+f"(d[0]), "+f"(d[1]), "+f"(d[2]), "+f"(d[3])
                 : "r"(a[0]), "r"(a[1]), "r"(a[2]), "r"(a[3]),
                   "r"(b[0]), "r"(b[1]));
}

// split 8 fp32 -> 8 bf16 hi (uint4) + 8 bf16 lo (uint4)
__device__ __forceinline__ void split8(float4 f0, float4 f1, uint4& hi, uint4& lo) {
    float e[8] = { f0.x, f0.y, f0.z, f0.w, f1.x, f1.y, f1.z, f1.w };
    u32 h[4], l[4];
#pragma unroll
    for (int i = 0; i < 4; ++i) {
        float a = e[2 * i], b = e[2 * i + 1];
        u32 hp; asm("cvt.rn.bf16x2.f32 %0, %1, %2;" : "=r"(hp) : "f"(b), "f"(a));
        float ha = __uint_as_float((hp & 0xFFFFu) << 16);
        float hb = __uint_as_float(hp & 0xFFFF0000u);
        float ra = a - ha, rb = b - hb;
        u32 lp; asm("cvt.rn.bf16x2.f32 %0, %1, %2;" : "=r"(lp) : "f"(rb), "f"(ra));
        h[i] = hp; l[i] = lp;
    }
    hi = make_uint4(h[0], h[1], h[2], h[3]);
    lo = make_uint4(l[0], l[1], l[2], l[3]);
}

// ---------------------------------------------------------------------------
// conv_split: fp32 [rows][256] -> bf16 [rows][512] (hi cols 0..255, lo 256..511)
// ---------------------------------------------------------------------------
__global__ void conv_split(const float* __restrict__ src, bf16* __restrict__ dst,
                           int rows)
{
    const int idx = blockIdx.x * 256 + threadIdx.x;
    const int row = idx >> 5;
    if (row >= rows) return;
    const int c = (idx & 31) * 8;
    const float* s = src + (size_t)row * 256 + c;
    float4 f0 = *(const float4*)s, f1 = *(const float4*)(s + 4);
    uint4 hi, lo; split8(f0, f1, hi, lo);
    *(uint4*)&dst[(size_t)row * 512 + c]       = hi;
    *(uint4*)&dst[(size_t)row * 512 + 256 + c] = lo;
}

// ---------------------------------------------------------------------------
// GEMM core. A [M][512] bf16 hi|lo, B [N][512] bf16 hi|lo (weights, K-major).
// C = Ahi*Bhi^T + Alo*Bhi^T + Ahi*Blo^T  (fp32 accum).
// smem: per K-chunk(64): Ahi MB rows x 144B | Alo | Bhi NB x 144B | Blo,
// double-buffered via cp.async. Warp tile 32x64, m16n8k16 mma.
// ---------------------------------------------------------------------------
template<int MB, int NB, int NTH>
__device__ __forceinline__ void load_chunk(u32 sb, const bf16* __restrict__ A,
                                           const bf16* __restrict__ B, int m0, int kc)
{
    const int tid = threadIdx.x;
    constexpr u32 AREG = MB * 144u;
    constexpr u32 BREG = NB * 144u;
#pragma unroll
    for (int i = tid; i < MB * 16; i += NTH) {
        const int h = i >= MB * 8;
        const int j = i - h * MB * 8;
        const int r = j >> 3, s = j & 7;
        cpa16(sb + h * AREG + r * 144 + s * 16,
              A + ((size_t)(m0 + r) << 9) + h * 256 + kc * 64 + s * 8);
    }
#pragma unroll
    for (int i = tid; i < NB * 16; i += NTH) {
        const int h = i >= NB * 8;
        const int j = i - h * NB * 8;
        const int r = j >> 3, s = j & 7;
        cpa16(sb + 2 * AREG + h * BREG + r * 144 + s * 16,
              B + ((size_t)r << 9) + h * 256 + kc * 64 + s * 8);
    }
}

template<int MB, int NB>
__device__ __forceinline__ void mma_chunk(u32 sb, int wm, int wn, int lane,
                                          float c[2][8][4])
{
    constexpr u32 AREG = MB * 144u;
    constexpr u32 OFF_BHI = 2 * AREG;
    constexpr u32 OFF_BLO = OFF_BHI + NB * 144u;
    const u32 arow  = lane & 15;
    const u32 ahalf = (lane >> 4) * 16;
#pragma unroll
    for (int ks = 0; ks < 4; ++ks) {
        const u32 kb = ks * 32 + ahalf;
        u32 ah[2][4], al[2][4];
#pragma unroll
        for (int t = 0; t < 2; ++t) {
            const u32 ad = sb + (wm * 32 + t * 16 + arow) * 144 + kb;
            LDSM4(ah[t][0], ah[t][1], ah[t][2], ah[t][3], ad);
            LDSM4(al[t][0], al[t][1], al[t][2], al[t][3], ad + AREG);
        }
#pragma unroll
        for (int p = 0; p < 4; ++p) {
            const u32 bd = sb + OFF_BHI + (wn * 64 + p * 16 + arow) * 144 + kb;
            u32 m0r, m1r, m2r, m3r;
            LDSM4(m0r, m1r, m2r, m3r, bd);
            u32 b0[2] = { m0r, m2r }, b1[2] = { m1r, m3r };
#pragma unroll
            for (int t = 0; t < 2; ++t) {
                mma_bf16(c[t][2 * p],     ah[t], b0);
                mma_bf16(c[t][2 * p + 1], ah[t], b1);
                mma_bf16(c[t][2 * p],     al[t], b0);
                mma_bf16(c[t][2 * p + 1], al[t], b1);
            }
        }
#pragma unroll
        for (int p = 0; p < 4; ++p) {
            const u32 bd = sb + OFF_BLO + (wn * 64 + p * 16 + arow) * 144 + kb;
            u32 m0r, m1r, m2r, m3r;
            LDSM4(m0r, m1r, m2r, m3r, bd);
            u32 b0[2] = { m0r, m2r }, b1[2] = { m1r, m3r };
#pragma unroll
            for (int t = 0; t < 2; ++t) {
                mma_bf16(c[t][2 * p],     ah[t], b0);
                mma_bf16(c[t][2 * p + 1], ah[t], b1);
            }
        }
    }
}

template<int MB, int NB, int NTH>
__device__ __forceinline__ void gemm_pipe(u32 sb, const bf16* __restrict__ A,
                                          const bf16* __restrict__ B, int m0,
                                          int wm, int wn, int lane, float c[2][8][4])
{
    constexpr u32 CHUNK = 2 * MB * 144u + 2 * NB * 144u;
    load_chunk<MB, NB, NTH>(sb, A, B, m0, 0);         CP_COMMIT();
    load_chunk<MB, NB, NTH>(sb + CHUNK, A, B, m0, 1); CP_COMMIT();
#pragma unroll
    for (int kc = 0; kc < 4; ++kc) {
        if (kc < 3) { CP_WAIT(1); } else { CP_WAIT(0); }
        __syncthreads();
        mma_chunk<MB, NB>(sb + (kc & 1) * CHUNK, wm, wn, lane, c);
        __syncthreads();
        if (kc < 2) {
            load_chunk<MB, NB, NTH>(sb + (kc & 1) * CHUNK, A, B, m0, kc + 2);
            CP_COMMIT();
        }
    }
}

// ---------------------------------------------------------------------------
// QKV GEMM: grid = 64 mtiles x 6 ntiles. ntile<2 -> Q (A=acts); else K/V (A=edges).
// CTA 128x128, 256 threads (warps 4x2).
// ---------------------------------------------------------------------------
#define SMEM_QKV (2 * (2 * 128 * 144 + 2 * 128 * 144))

__global__ __launch_bounds__(256, 1)
void qkv_mma(const bf16* __restrict__ Ain, const bf16* __restrict__ Ein,
             const bf16* __restrict__ W, const float* __restrict__ bias,
             float* __restrict__ Qo, float* __restrict__ KVo)
{
    extern __shared__ char smem[];
    const u32 sb = smem_u32(smem);
    const int mtile = blockIdx.x & 63, ntile = blockIdx.x >> 6;
    const int m0 = mtile * 128, n0 = ntile * 128;
    const bf16* A = (ntile < 2) ? Ain : Ein;
    const bf16* B = W + (size_t)n0 * 512;
    const int wid = threadIdx.x >> 5, lane = threadIdx.x & 31;
    const int wm = wid >> 1, wn = wid & 1;

    float c[2][8][4] = {};
    gemm_pipe<128, 128, 256>(sb, A, B, m0, wm, wn, lane, c);

    float* C; int ldc, cb;
    if (ntile < 2) { C = Qo;  ldc = 256; cb = n0; }
    else           { C = KVo; ldc = 512; cb = n0 - 256; }

#pragma unroll
    for (int t = 0; t < 2; ++t) {
#pragma unroll
        for (int u = 0; u < 8; ++u) {
            const int row = m0 + wm * 32 + t * 16 + (lane >> 2);
            const int col = wn * 64 + u * 8 + (lane & 3) * 2;
            const float b0 = bias[n0 + col], b1 = bias[n0 + col + 1];
            float* p = C + (size_t)row * ldc + cb + col;
            *(float2*)p             = make_float2(c[t][u][0] + b0, c[t][u][1] + b1);
            *(float2*)(p + 8 * ldc) = make_float2(c[t][u][2] + b0, c[t][u][3] + b1);
        }
    }
}

// ---------------------------------------------------------------------------
// Out-proj GEMM + bias + residual + LayerNorm. CTA 64x256 (full row), grid 128.
// 256 threads (warps 2x4). Epilogue: stash -> row LN -> fp32 out (+ bf16 split).
// ---------------------------------------------------------------------------
#define SMEM_OUT (2 * (2 * 64 * 144 + 2 * 256 * 144))

__global__ __launch_bounds__(256, 1)
void outln_mma(const bf16* __restrict__ A, const bf16* __restrict__ W,
               const float* __restrict__ bias, const float* __restrict__ resid,
               const float* __restrict__ gg, const float* __restrict__ bb,
               float* __restrict__ out, bf16* __restrict__ xc)
{
    extern __shared__ char smem[];
    const u32 sb = smem_u32(smem);
    const int m0 = blockIdx.x * 64;
    const int wid = threadIdx.x >> 5, lane = threadIdx.x & 31;
    const int wm = wid & 1, wn = wid >> 1;

    float c[2][8][4] = {};
    gemm_pipe<64, 256, 256>(sb, A, W, m0, wm, wn, lane, c);

    float* stash = (float*)smem;   // 64 rows x 264 floats
#pragma unroll
    for (int t = 0; t < 2; ++t) {
#pragma unroll
        for (int u = 0; u < 8; ++u) {
            const int r = wm * 32 + t * 16 + (lane >> 2);
            const int col = wn * 64 + u * 8 + (lane & 3) * 2;
            const float b0 = bias[col], b1 = bias[col + 1];
            *(float2*)&stash[(size_t)r * 264 + col] =
                make_float2(c[t][u][0] + b0, c[t][u][1] + b1);
            *(float2*)&stash[(size_t)(r + 8) * 264 + col] =
                make_float2(c[t][u][2] + b0, c[t][u][3] + b1);
        }
    }
    __syncthreads();

#pragma unroll
    for (int i = 0; i < 8; ++i) {
        const int r = wid * 8 + i;          // 0..63
        const int grow = m0 + r;
        const int c0 = lane * 8;
        float4 s0 = *(const float4*)&stash[(size_t)r * 264 + c0];
        float4 s1 = *(const float4*)&stash[(size_t)r * 264 + c0 + 4];
        const float* rp = resid + (size_t)grow * EDIM + c0;
        float4 r0 = *(const float4*)rp, r1 = *(const float4*)(rp + 4);
        float v[8] = { s0.x + r0.x, s0.y + r0.y, s0.z + r0.z, s0.w + r0.w,
                       s1.x + r1.x, s1.y + r1.y, s1.z + r1.z, s1.w + r1.w };
        float s = 0.f, ss = 0.f;
#pragma unroll
        for (int j = 0; j < 8; ++j) { s += v[j]; ss += v[j] * v[j]; }
#pragma unroll
        for (int d = 16; d; d >>= 1) {
            s  += __shfl_xor_sync(0xffffffffu, s,  d);
            ss += __shfl_xor_sync(0xffffffffu, ss, d);
        }
        const float m   = s * (1.f / 256.f);
        const float var = ss * (1.f / 256.f) - m * m;
        const float inv = rsqrtf(var + 1e-5f);

        float4 g0 = *(const float4*)(gg + c0), g1 = *(const float4*)(gg + c0 + 4);
        float4 b0 = *(const float4*)(bb + c0), b1 = *(const float4*)(bb + c0 + 4);
        float o[8];
        o[0] = (v[0] - m) * inv * g0.x + b0.x; o[1] = (v[1] - m) * inv * g0.y + b0.y;
        o[2] = (v[2] - m) * inv * g0.z + b0.z; o[3] = (v[3] - m) * inv * g0.w + b0.w;
        o[4] = (v[4] - m) * inv * g1.x + b1.x; o[5] = (v[5] - m) * inv * g1.y + b1.y;
        o[6] = (v[6] - m) * inv * g1.z + b1.z; o[7] = (v[7] - m) * inv * g1.w + b1.w;

        float* op = out + (size_t)grow * EDIM + c0;
        *(float4*)op       = make_float4(o[0], o[1], o[2], o[3]);
        *(float4*)(op + 4) = make_float4(o[4], o[5], o[6], o[7]);

        if (xc) {
            uint4 hi, lo;
            split8(make_float4(o[0], o[1], o[2], o[3]),
                   make_float4(o[4], o[5], o[6], o[7]), hi, lo);
            *(uint4*)&xc[(size_t)grow * 512 + c0]       = hi;
            *(uint4*)&xc[(size_t)grow * 512 + 256 + c0] = lo;
        }
    }
}

// ---------------------------------------------------------------------------
// Attention: one warp per face; emits bf16 hi|lo output directly.
// ---------------------------------------------------------------------------
__global__ __launch_bounds__(256)
void attn_kernel(const int* __restrict__ loop, const float* __restrict__ Q,
                 const float* __restrict__ KV, bf16* __restrict__ attc)
{
    const int warp = threadIdx.x >> 5;
    const int lane = threadIdx.x & 31;
    const int face = (blockIdx.x << 3) + warp;

    __shared__ int sidx[8][16];
    if (lane < 16) sidx[warp][lane] = loop[face * MAXLOOP + lane];
    __syncwarp();

    bool v = false;
    if (lane < 16) {
        const int my = sidx[warp][lane];
        v = (my >= 0);
        for (int j = 0; v && j < lane; ++j)
            if (sidx[warp][j] == my) v = false;
    }
    const unsigned bal = __ballot_sync(0xffffffffu, v);

    const float scale = 0.08838834764831845f;  // 1/sqrt(128)
    const float* qp = Q + (size_t)face * EDIM + lane * 8;
    float4 q0 = *(const float4*)qp;
    float4 q1 = *(const float4*)(qp + 4);
    q0.x *= scale; q0.y *= scale; q0.z *= scale; q0.w *= scale;
    q1.x *= scale; q1.y *= scale; q1.z *= scale; q1.w *= scale;

    float myscore = -3e38f;
#pragma unroll
    for (int i = 0; i < 16; ++i) {
        if (!(bal & (1u << i))) continue;
        const int idx = sidx[warp][i];
        const float* kp = KV + (size_t)idx * 512 + lane * 8;
        float4 k0 = *(const float4*)kp;
        float4 k1 = *(const float4*)(kp + 4);
        float p = q0.x * k0.x + q0.y * k0.y + q0.z * k0.z + q0.w * k0.w
                + q1.x * k1.x + q1.y * k1.y + q1.z * k1.z + q1.w * k1.w;
        p += __shfl_xor_sync(0xffffffffu, p, 8);
        p += __shfl_xor_sync(0xffffffffu, p, 4);
        p += __shfl_xor_sync(0xffffffffu, p, 2);
        p += __shfl_xor_sync(0xffffffffu, p, 1);
        if ((lane & 15) == i) myscore = p;
    }

    const bool mv = (bal >> (lane & 15)) & 1u;
    float s = mv ? myscore : -3e38f;
    float mx = s;
#pragma unroll
    for (int d = 8; d; d >>= 1) mx = fmaxf(mx, __shfl_xor_sync(0xffffffffu, mx, d));
    float e = mv ? __expf(s - mx) : 0.f;
    float sum = e;
#pragma unroll
    for (int d = 8; d; d >>= 1) sum += __shfl_xor_sync(0xffffffffu, sum, d);
    const float w = e / sum;

    float a0=0.f,a1=0.f,a2=0.f,a3=0.f,a4=0.f,a5=0.f,a6=0.f,a7=0.f;
    const int hb = lane & 16;
#pragma unroll
    for (int i = 0; i < 16; ++i) {
        if (!(bal & (1u << i))) continue;
        const int idx = sidx[warp][i];
        const float wi = __shfl_sync(0xffffffffu, w, hb | i);
        const float* vp = KV + (size_t)idx * 512 + 256 + lane * 8;
        float4 v0 = *(const float4*)vp;
        float4 v1 = *(const float4*)(vp + 4);
        a0 = fmaf(wi, v0.x, a0); a1 = fmaf(wi, v0.y, a1);
        a2 = fmaf(wi, v0.z, a2); a3 = fmaf(wi, v0.w, a3);
        a4 = fmaf(wi, v1.x, a4); a5 = fmaf(wi, v1.y, a5);
        a6 = fmaf(wi, v1.z, a6); a7 = fmaf(wi, v1.w, a7);
    }
    uint4 hi, lo;
    split8(make_float4(a0, a1, a2, a3), make_float4(a4, a5, a6, a7), hi, lo);
    *(uint4*)&attc[(size_t)face * 512 + lane * 8]       = hi;
    *(uint4*)&attc[(size_t)face * 512 + 256 + lane * 8] = lo;
}

// ---------------------------------------------------------------------------
extern "C" void kernel_launch(void* const* d_in, const int* in_sizes, int n_in,
                              void* d_out, int out_size)
{
    const int*   loop  = (const int*)  d_in[0];
    const float* edge  = (const float*)d_in[2];
    const float* face  = (const float*)d_in[3];
    const float* w_in1  = (const float*)d_in[4];
    const float* b_in1  = (const float*)d_in[5];
    const float* w_out1 = (const float*)d_in[6];
    const float* b_out1 = (const float*)d_in[7];
    const float* ln1_g  = (const float*)d_in[8];
    const float* ln1_b  = (const float*)d_in[9];
    const float* w_in2  = (const float*)d_in[10];
    const float* b_in2  = (const float*)d_in[11];
    const float* w_out2 = (const float*)d_in[12];
    const float* b_out2 = (const float*)d_in[13];
    const float* ln2_g  = (const float*)d_in[14];
    const float* ln2_b  = (const float*)d_in[15];

    float *Q, *KV, *X;
    bf16 *Ac, *Ec, *ATTc, *Wc1, *Wc2, *Wo1, *Wo2;
    cudaGetSymbolAddress((void**)&Q,    g_Q);
    cudaGetSymbolAddress((void**)&KV,   g_KV);
    cudaGetSymbolAddress((void**)&X,    g_X);
    cudaGetSymbolAddress((void**)&Ac,   g_Ac);
    cudaGetSymbolAddress((void**)&Ec,   g_Ec);
    cudaGetSymbolAddress((void**)&ATTc, g_ATTc);
    cudaGetSymbolAddress((void**)&Wc1,  g_Wc1);
    cudaGetSymbolAddress((void**)&Wc2,  g_Wc2);
    cudaGetSymbolAddress((void**)&Wo1,  g_Wo1);
    cudaGetSymbolAddress((void**)&Wo2,  g_Wo2);

    cudaFuncSetAttribute(qkv_mma,   cudaFuncAttributeMaxDynamicSharedMemorySize, SMEM_QKV);
    cudaFuncSetAttribute(outln_mma, cudaFuncAttributeMaxDynamicSharedMemorySize, SMEM_OUT);

    // pre-split inputs and weights to bf16 hi|lo
    conv_split<<<1024, 256>>>(face,   Ac,  8192);
    conv_split<<<1024, 256>>>(edge,   Ec,  8192);
    conv_split<<<96,   256>>>(w_in1,  Wc1, 768);
    conv_split<<<32,   256>>>(w_out1, Wo1, 256);
    conv_split<<<96,   256>>>(w_in2,  Wc2, 768);
    conv_split<<<32,   256>>>(w_out2, Wo2, 256);

    // ---- layer 1 ----
    qkv_mma    <<<384, 256, SMEM_QKV>>>(Ac, Ec, Wc1, b_in1, Q, KV);
    attn_kernel<<<1024, 256>>>(loop, Q, KV, ATTc);
    outln_mma  <<<128, 256, SMEM_OUT>>>(ATTc, Wo1, b_out1, face, ln1_g, ln1_b, X, Ac);

    // ---- layer 2 ----
    qkv_mma    <<<384, 256, SMEM_QKV>>>(Ac, Ec, Wc2, b_in2, Q, KV);
    attn_kernel<<<1024, 256>>>(loop, Q, KV, ATTc);
    outln_mma  <<<128, 256, SMEM_OUT>>>(ATTc, Wo2, b_out2, X, ln2_g, ln2_b,
                                        (float*)d_out, (bf16*)nullptr);
}

// round 5
// speedup vs baseline: 2.8404x; 1.3840x over previous
#include <cuda_runtime.h>
#include <cuda_fp16.h>
#include <cstdint>

typedef unsigned int u32;
typedef __half half_t;

#define EDIM    256
#define MAXLOOP 16

// ---------------------------------------------------------------------------
// Global scratch (no allocation allowed)
// ---------------------------------------------------------------------------
__device__ float  g_Q  [8192 * 256];
__device__ half_t g_KV [8192 * 512];       // fp16: K cols 0..255, V cols 256..511
__device__ float  g_X  [8192 * 256];
__device__ half_t g_Ac [8192 * 512];       // activations hi|lo fp16 (face, then X)
__device__ half_t g_Ec [8192 * 512];       // edges hi|lo fp16
__device__ half_t g_ATTc[8192 * 512];      // attention out hi|lo fp16
__device__ half_t g_Wc1[768 * 256];        // weights fp16 (hi only)
__device__ half_t g_Wc2[768 * 256];
__device__ half_t g_Wo1[256 * 256];
__device__ half_t g_Wo2[256 * 256];

// ---------------------------------------------------------------------------
// Helpers (plain sm_80+ features only — harness lowers to compute_103 PTX)
// ---------------------------------------------------------------------------
__device__ __forceinline__ u32 smem_u32(const void* p) {
    u32 a; asm("{ .reg .u64 t; cvta.to.shared.u64 t, %1; cvt.u32.u64 %0, t; }"
               : "=r"(a) : "l"(p));
    return a;
}
__device__ __forceinline__ void cpa16(u32 d, const void* s) {
    asm volatile("cp.async.ca.shared.global [%0], [%1], 16;" :: "r"(d), "l"(s));
}
#define CP_COMMIT() asm volatile("cp.async.commit_group;" ::: "memory")
#define CP_WAIT(n)  asm volatile("cp.async.wait_group %0;" :: "n"(n) : "memory")
#define LDSM4(r0, r1, r2, r3, a) \
    asm volatile("ldmatrix.sync.aligned.m8n8.x4.shared.b16 {%0,%1,%2,%3}, [%4];" \
                 : "=r"(r0), "=r"(r1), "=r"(r2), "=r"(r3) : "r"(a))

__device__ __forceinline__ void mma_f16(float* d, const u32* a, const u32* b) {
    asm volatile("mma.sync.aligned.m16n8k16.row.col.f32.f16.f16.f32 "
                 "{%0,%1,%2,%3}, {%4,%5,%6,%7}, {%8,%9}, {%0,%1,%2,%3};"
                 : "+f"(d[0]), "+f"(d[1]), "+f"(d[2]), "+f"(d[3])
                 : "r"(a[0]), "r"(a[1]), "r"(a[2]), "r"(a[3]),
                   "r"(b[0]), "r"(b[1]));
}

__device__ __forceinline__ u32 h2u(__half2 h) { return *reinterpret_cast<u32*>(&h); }
__device__ __forceinline__ __half2 u2h(u32 u) { return *reinterpret_cast<__half2*>(&u); }

// split 8 fp32 -> 8 fp16 hi (uint4) + 8 fp16 lo (uint4)
__device__ __forceinline__ void split8h(float4 f0, float4 f1, uint4& hi, uint4& lo) {
    float e[8] = { f0.x, f0.y, f0.z, f0.w, f1.x, f1.y, f1.z, f1.w };
    u32 h[4], l[4];
#pragma unroll
    for (int i = 0; i < 4; ++i) {
        float a = e[2 * i], b = e[2 * i + 1];
        __half2 hp = __floats2half2_rn(a, b);
        float2 bk = __half22float2(hp);
        __half2 lp = __floats2half2_rn(a - bk.x, b - bk.y);
        h[i] = h2u(hp); l[i] = h2u(lp);
    }
    hi = make_uint4(h[0], h[1], h[2], h[3]);
    lo = make_uint4(l[0], l[1], l[2], l[3]);
}

// round 8 fp32 -> 8 fp16 (uint4)
__device__ __forceinline__ uint4 round8h(float4 f0, float4 f1) {
    return make_uint4(h2u(__floats2half2_rn(f0.x, f0.y)),
                      h2u(__floats2half2_rn(f0.z, f0.w)),
                      h2u(__floats2half2_rn(f1.x, f1.y)),
                      h2u(__floats2half2_rn(f1.z, f1.w)));
}

// ---------------------------------------------------------------------------
// conv_act: face + edge fp32 [8192][256] -> fp16 hi|lo [8192][512]
// ---------------------------------------------------------------------------
__global__ void conv_act(const float* __restrict__ f, const float* __restrict__ e,
                         half_t* __restrict__ Ac, half_t* __restrict__ Ec)
{
    const int idx = blockIdx.x * 256 + threadIdx.x;
    int row = idx >> 5;
    const int c = (idx & 31) * 8;
    const float* src; half_t* dst;
    if (row < 8192) { src = f; dst = Ac; }
    else            { src = e; dst = Ec; row -= 8192; }
    const float* s = src + (size_t)row * 256 + c;
    float4 f0 = *(const float4*)s, f1 = *(const float4*)(s + 4);
    uint4 hi, lo; split8h(f0, f1, hi, lo);
    *(uint4*)&dst[(size_t)row * 512 + c]       = hi;
    *(uint4*)&dst[(size_t)row * 512 + 256 + c] = lo;
}

// ---------------------------------------------------------------------------
// conv_wts: all four weight matrices fp32 -> fp16 in one launch (2048 rows)
// ---------------------------------------------------------------------------
__global__ void conv_wts(const float* __restrict__ w1, const float* __restrict__ o1,
                         const float* __restrict__ w2, const float* __restrict__ o2,
                         half_t* __restrict__ W1, half_t* __restrict__ O1,
                         half_t* __restrict__ W2, half_t* __restrict__ O2)
{
    const int idx = blockIdx.x * 256 + threadIdx.x;
    int row = idx >> 5;
    const int c = (idx & 31) * 8;
    const float* src; half_t* dst;
    if      (row < 768)  { src = w1; dst = W1; }
    else if (row < 1024) { src = o1; dst = O1; row -= 768; }
    else if (row < 1792) { src = w2; dst = W2; row -= 1024; }
    else                 { src = o2; dst = O2; row -= 1792; }
    const float* s = src + (size_t)row * 256 + c;
    float4 f0 = *(const float4*)s, f1 = *(const float4*)(s + 4);
    *(uint4*)&dst[(size_t)row * 256 + c] = round8h(f0, f1);
}

// ---------------------------------------------------------------------------
// GEMM core: A [M][512] fp16 hi|lo, B [N][256] fp16.
// C = Ahi*B^T + Alo*B^T (fp32 accum). K-chunk 64, double-buffered cp.async.
// smem chunk: Ahi MBx144 | Alo MBx144 | B NBx144. Warp tile 32x64.
// ---------------------------------------------------------------------------
template<int MB, int NB, int NTH>
__device__ __forceinline__ void load_chunk(u32 sb, const half_t* __restrict__ A,
                                           const half_t* __restrict__ B, int m0, int kc)
{
    const int tid = threadIdx.x;
    constexpr u32 AREG = MB * 144u;
#pragma unroll
    for (int i = tid; i < MB * 16; i += NTH) {
        const int h = i >= MB * 8;
        const int j = i - h * MB * 8;
        const int r = j >> 3, s = j & 7;
        cpa16(sb + h * AREG + r * 144 + s * 16,
              A + ((size_t)(m0 + r) << 9) + h * 256 + kc * 64 + s * 8);
    }
#pragma unroll
    for (int i = tid; i < NB * 8; i += NTH) {
        const int r = i >> 3, s = i & 7;
        cpa16(sb + 2 * AREG + r * 144 + s * 16,
              B + ((size_t)r << 8) + kc * 64 + s * 8);
    }
}

template<int MB, int NB>
__device__ __forceinline__ void mma_chunk(u32 sb, int wm, int wn, int lane,
                                          float c[2][8][4])
{
    constexpr u32 AREG = MB * 144u;
    constexpr u32 OFF_B = 2 * AREG;
    const u32 arow  = lane & 15;
    const u32 ahalf = (lane >> 4) * 16;
#pragma unroll
    for (int ks = 0; ks < 4; ++ks) {
        const u32 kb = ks * 32 + ahalf;
        u32 ah[2][4], al[2][4];
#pragma unroll
        for (int t = 0; t < 2; ++t) {
            const u32 ad = sb + (wm * 32 + t * 16 + arow) * 144 + kb;
            LDSM4(ah[t][0], ah[t][1], ah[t][2], ah[t][3], ad);
            LDSM4(al[t][0], al[t][1], al[t][2], al[t][3], ad + AREG);
        }
#pragma unroll
        for (int p = 0; p < 4; ++p) {
            const u32 bd = sb + OFF_B + (wn * 64 + p * 16 + arow) * 144 + kb;
            u32 m0r, m1r, m2r, m3r;
            LDSM4(m0r, m1r, m2r, m3r, bd);
            u32 b0[2] = { m0r, m2r }, b1[2] = { m1r, m3r };
#pragma unroll
            for (int t = 0; t < 2; ++t) {
                mma_f16(c[t][2 * p],     ah[t], b0);
                mma_f16(c[t][2 * p + 1], ah[t], b1);
                mma_f16(c[t][2 * p],     al[t], b0);
                mma_f16(c[t][2 * p + 1], al[t], b1);
            }
        }
    }
}

template<int MB, int NB, int NTH>
__device__ __forceinline__ void gemm_pipe(u32 sb, const half_t* __restrict__ A,
                                          const half_t* __restrict__ B, int m0,
                                          int wm, int wn, int lane, float c[2][8][4])
{
    constexpr u32 CHUNK = (2 * MB + NB) * 144u;
    load_chunk<MB, NB, NTH>(sb, A, B, m0, 0);         CP_COMMIT();
    load_chunk<MB, NB, NTH>(sb + CHUNK, A, B, m0, 1); CP_COMMIT();
#pragma unroll
    for (int kc = 0; kc < 4; ++kc) {
        if (kc < 3) { CP_WAIT(1); } else { CP_WAIT(0); }
        __syncthreads();
        mma_chunk<MB, NB>(sb + (kc & 1) * CHUNK, wm, wn, lane, c);
        __syncthreads();
        if (kc < 2) {
            load_chunk<MB, NB, NTH>(sb + (kc & 1) * CHUNK, A, B, m0, kc + 2);
            CP_COMMIT();
        }
    }
}

// ---------------------------------------------------------------------------
// QKV GEMM: grid = 64 mtiles x 6 ntiles. ntile<2 -> Q fp32 (A=acts);
// ntile>=2 -> K/V fp16 (A=edges). CTA 128x128, 256 threads.
// ---------------------------------------------------------------------------
#define SMEM_QKV (2 * ((2 * 128 + 128) * 144))

__global__ __launch_bounds__(256, 1)
void qkv_mma(const half_t* __restrict__ Ain, const half_t* __restrict__ Ein,
             const half_t* __restrict__ W, const float* __restrict__ bias,
             float* __restrict__ Qo, half_t* __restrict__ KVo)
{
    extern __shared__ char smem[];
    const u32 sb = smem_u32(smem);
    const int mtile = blockIdx.x & 63, ntile = blockIdx.x >> 6;
    const int m0 = mtile * 128, n0 = ntile * 128;
    const half_t* A = (ntile < 2) ? Ain : Ein;
    const half_t* B = W + (size_t)n0 * 256;
    const int wid = threadIdx.x >> 5, lane = threadIdx.x & 31;
    const int wm = wid >> 1, wn = wid & 1;

    float c[2][8][4] = {};
    gemm_pipe<128, 128, 256>(sb, A, B, m0, wm, wn, lane, c);

    if (ntile < 2) {
#pragma unroll
        for (int t = 0; t < 2; ++t)
#pragma unroll
            for (int u = 0; u < 8; ++u) {
                const int row = m0 + wm * 32 + t * 16 + (lane >> 2);
                const int col = wn * 64 + u * 8 + (lane & 3) * 2;
                const float b0 = bias[n0 + col], b1 = bias[n0 + col + 1];
                float* p = Qo + (size_t)row * 256 + n0 + col;
                *(float2*)p              = make_float2(c[t][u][0] + b0, c[t][u][1] + b1);
                *(float2*)(p + 8 * 256)  = make_float2(c[t][u][2] + b0, c[t][u][3] + b1);
            }
    } else {
        const int cb = n0 - 256;
#pragma unroll
        for (int t = 0; t < 2; ++t)
#pragma unroll
            for (int u = 0; u < 8; ++u) {
                const int row = m0 + wm * 32 + t * 16 + (lane >> 2);
                const int col = wn * 64 + u * 8 + (lane & 3) * 2;
                const float b0 = bias[n0 + col], b1 = bias[n0 + col + 1];
                half_t* p = KVo + (size_t)row * 512 + cb + col;
                *(__half2*)p             = __floats2half2_rn(c[t][u][0] + b0, c[t][u][1] + b1);
                *(__half2*)(p + 8 * 512) = __floats2half2_rn(c[t][u][2] + b0, c[t][u][3] + b1);
            }
    }
}

// ---------------------------------------------------------------------------
// Out-proj GEMM + bias + residual + LayerNorm. CTA 64x256 (full row), grid 128.
// ---------------------------------------------------------------------------
#define SMEM_OUT (2 * ((2 * 64 + 256) * 144))

__global__ __launch_bounds__(256, 1)
void outln_mma(const half_t* __restrict__ A, const half_t* __restrict__ W,
               const float* __restrict__ bias, const float* __restrict__ resid,
               const float* __restrict__ gg, const float* __restrict__ bb,
               float* __restrict__ out, half_t* __restrict__ xc)
{
    extern __shared__ char smem[];
    const u32 sb = smem_u32(smem);
    const int m0 = blockIdx.x * 64;
    const int wid = threadIdx.x >> 5, lane = threadIdx.x & 31;
    const int wm = wid & 1, wn = wid >> 1;

    float c[2][8][4] = {};
    gemm_pipe<64, 256, 256>(sb, A, W, m0, wm, wn, lane, c);

    float* stash = (float*)smem;   // 64 rows x 264 floats
#pragma unroll
    for (int t = 0; t < 2; ++t)
#pragma unroll
        for (int u = 0; u < 8; ++u) {
            const int r = wm * 32 + t * 16 + (lane >> 2);
            const int col = wn * 64 + u * 8 + (lane & 3) * 2;
            const float b0 = bias[col], b1 = bias[col + 1];
            *(float2*)&stash[(size_t)r * 264 + col] =
                make_float2(c[t][u][0] + b0, c[t][u][1] + b1);
            *(float2*)&stash[(size_t)(r + 8) * 264 + col] =
                make_float2(c[t][u][2] + b0, c[t][u][3] + b1);
        }
    __syncthreads();

#pragma unroll
    for (int i = 0; i < 8; ++i) {
        const int r = wid * 8 + i;          // 0..63
        const int grow = m0 + r;
        const int c0 = lane * 8;
        float4 s0 = *(const float4*)&stash[(size_t)r * 264 + c0];
        float4 s1 = *(const float4*)&stash[(size_t)r * 264 + c0 + 4];
        const float* rp = resid + (size_t)grow * EDIM + c0;
        float4 r0 = *(const float4*)rp, r1 = *(const float4*)(rp + 4);
        float v[8] = { s0.x + r0.x, s0.y + r0.y, s0.z + r0.z, s0.w + r0.w,
                       s1.x + r1.x, s1.y + r1.y, s1.z + r1.z, s1.w + r1.w };
        float s = 0.f, ss = 0.f;
#pragma unroll
        for (int j = 0; j < 8; ++j) { s += v[j]; ss += v[j] * v[j]; }
#pragma unroll
        for (int d = 16; d; d >>= 1) {
            s  += __shfl_xor_sync(0xffffffffu, s,  d);
            ss += __shfl_xor_sync(0xffffffffu, ss, d);
        }
        const float m   = s * (1.f / 256.f);
        const float var = ss * (1.f / 256.f) - m * m;
        const float inv = rsqrtf(var + 1e-5f);

        float4 g0 = *(const float4*)(gg + c0), g1 = *(const float4*)(gg + c0 + 4);
        float4 b0 = *(const float4*)(bb + c0), b1 = *(const float4*)(bb + c0 + 4);
        float o[8];
        o[0] = (v[0] - m) * inv * g0.x + b0.x; o[1] = (v[1] - m) * inv * g0.y + b0.y;
        o[2] = (v[2] - m) * inv * g0.z + b0.z; o[3] = (v[3] - m) * inv * g0.w + b0.w;
        o[4] = (v[4] - m) * inv * g1.x + b1.x; o[5] = (v[5] - m) * inv * g1.y + b1.y;
        o[6] = (v[6] - m) * inv * g1.z + b1.z; o[7] = (v[7] - m) * inv * g1.w + b1.w;

        float* op = out + (size_t)grow * EDIM + c0;
        *(float4*)op       = make_float4(o[0], o[1], o[2], o[3]);
        *(float4*)(op + 4) = make_float4(o[4], o[5], o[6], o[7]);

        if (xc) {
            uint4 hi, lo;
            split8h(make_float4(o[0], o[1], o[2], o[3]),
                    make_float4(o[4], o[5], o[6], o[7]), hi, lo);
            *(uint4*)&xc[(size_t)grow * 512 + c0]       = hi;
            *(uint4*)&xc[(size_t)grow * 512 + 256 + c0] = lo;
        }
    }
}

// ---------------------------------------------------------------------------
// Attention: one warp per face; K/V fp16, Q fp32; emits fp16 hi|lo output.
// ---------------------------------------------------------------------------
__global__ __launch_bounds__(256)
void attn_kernel(const int* __restrict__ loop, const float* __restrict__ Q,
                 const half_t* __restrict__ KV, half_t* __restrict__ attc)
{
    const int warp = threadIdx.x >> 5;
    const int lane = threadIdx.x & 31;
    const int face = (blockIdx.x << 3) + warp;

    __shared__ int sidx[8][16];
    if (lane < 16) sidx[warp][lane] = loop[face * MAXLOOP + lane];
    __syncwarp();

    bool v = false;
    if (lane < 16) {
        const int my = sidx[warp][lane];
        v = (my >= 0);
        for (int j = 0; v && j < lane; ++j)
            if (sidx[warp][j] == my) v = false;
    }
    const unsigned bal = __ballot_sync(0xffffffffu, v);

    const float scale = 0.08838834764831845f;  // 1/sqrt(128)
    const float* qp = Q + (size_t)face * EDIM + lane * 8;
    float4 q0 = *(const float4*)qp;
    float4 q1 = *(const float4*)(qp + 4);
    float q[8] = { q0.x * scale, q0.y * scale, q0.z * scale, q0.w * scale,
                   q1.x * scale, q1.y * scale, q1.z * scale, q1.w * scale };

    float myscore = -3e38f;
#pragma unroll
    for (int i = 0; i < 16; ++i) {
        if (!(bal & (1u << i))) continue;
        const int idx = sidx[warp][i];
        uint4 kr = *(const uint4*)(KV + (size_t)idx * 512 + lane * 8);
        float2 k0 = __half22float2(u2h(kr.x)), k1 = __half22float2(u2h(kr.y));
        float2 k2 = __half22float2(u2h(kr.z)), k3 = __half22float2(u2h(kr.w));
        float p = q[0] * k0.x + q[1] * k0.y + q[2] * k1.x + q[3] * k1.y
                + q[4] * k2.x + q[5] * k2.y + q[6] * k3.x + q[7] * k3.y;
        p += __shfl_xor_sync(0xffffffffu, p, 8);
        p += __shfl_xor_sync(0xffffffffu, p, 4);
        p += __shfl_xor_sync(0xffffffffu, p, 2);
        p += __shfl_xor_sync(0xffffffffu, p, 1);
        if ((lane & 15) == i) myscore = p;
    }

    const bool mv = (bal >> (lane & 15)) & 1u;
    float s = mv ? myscore : -3e38f;
    float mx = s;
#pragma unroll
    for (int d = 8; d; d >>= 1) mx = fmaxf(mx, __shfl_xor_sync(0xffffffffu, mx, d));
    float e = mv ? __expf(s - mx) : 0.f;
    float sum = e;
#pragma unroll
    for (int d = 8; d; d >>= 1) sum += __shfl_xor_sync(0xffffffffu, sum, d);
    const float w = e / sum;

    float a[8] = {};
    const int hb = lane & 16;
#pragma unroll
    for (int i = 0; i < 16; ++i) {
        if (!(bal & (1u << i))) continue;
        const int idx = sidx[warp][i];
        const float wi = __shfl_sync(0xffffffffu, w, hb | i);
        uint4 vr = *(const uint4*)(KV + (size_t)idx * 512 + 256 + lane * 8);
        float2 v0 = __half22float2(u2h(vr.x)), v1 = __half22float2(u2h(vr.y));
        float2 v2 = __half22float2(u2h(vr.z)), v3 = __half22float2(u2h(vr.w));
        a[0] = fmaf(wi, v0.x, a[0]); a[1] = fmaf(wi, v0.y, a[1]);
        a[2] = fmaf(wi, v1.x, a[2]); a[3] = fmaf(wi, v1.y, a[3]);
        a[4] = fmaf(wi, v2.x, a[4]); a[5] = fmaf(wi, v2.y, a[5]);
        a[6] = fmaf(wi, v3.x, a[6]); a[7] = fmaf(wi, v3.y, a[7]);
    }
    uint4 hi, lo;
    split8h(make_float4(a[0], a[1], a[2], a[3]),
            make_float4(a[4], a[5], a[6], a[7]), hi, lo);
    *(uint4*)&attc[(size_t)face * 512 + lane * 8]       = hi;
    *(uint4*)&attc[(size_t)face * 512 + 256 + lane * 8] = lo;
}

// ---------------------------------------------------------------------------
extern "C" void kernel_launch(void* const* d_in, const int* in_sizes, int n_in,
                              void* d_out, int out_size)
{
    const int*   loop  = (const int*)  d_in[0];
    const float* edge  = (const float*)d_in[2];
    const float* face  = (const float*)d_in[3];
    const float* w_in1  = (const float*)d_in[4];
    const float* b_in1  = (const float*)d_in[5];
    const float* w_out1 = (const float*)d_in[6];
    const float* b_out1 = (const float*)d_in[7];
    const float* ln1_g  = (const float*)d_in[8];
    const float* ln1_b  = (const float*)d_in[9];
    const float* w_in2  = (const float*)d_in[10];
    const float* b_in2  = (const float*)d_in[11];
    const float* w_out2 = (const float*)d_in[12];
    const float* b_out2 = (const float*)d_in[13];
    const float* ln2_g  = (const float*)d_in[14];
    const float* ln2_b  = (const float*)d_in[15];

    float *Q, *X;
    half_t *KV, *Ac, *Ec, *ATTc, *Wc1, *Wc2, *Wo1, *Wo2;
    cudaGetSymbolAddress((void**)&Q,    g_Q);
    cudaGetSymbolAddress((void**)&KV,   g_KV);
    cudaGetSymbolAddress((void**)&X,    g_X);
    cudaGetSymbolAddress((void**)&Ac,   g_Ac);
    cudaGetSymbolAddress((void**)&Ec,   g_Ec);
    cudaGetSymbolAddress((void**)&ATTc, g_ATTc);
    cudaGetSymbolAddress((void**)&Wc1,  g_Wc1);
    cudaGetSymbolAddress((void**)&Wc2,  g_Wc2);
    cudaGetSymbolAddress((void**)&Wo1,  g_Wo1);
    cudaGetSymbolAddress((void**)&Wo2,  g_Wo2);

    cudaFuncSetAttribute(qkv_mma,   cudaFuncAttributeMaxDynamicSharedMemorySize, SMEM_QKV);
    cudaFuncSetAttribute(outln_mma, cudaFuncAttributeMaxDynamicSharedMemorySize, SMEM_OUT);

    conv_act<<<2048, 256>>>(face, edge, Ac, Ec);
    conv_wts<<<256, 256>>>(w_in1, w_out1, w_in2, w_out2, Wc1, Wo1, Wc2, Wo2);

    // ---- layer 1 ----
    qkv_mma    <<<384, 256, SMEM_QKV>>>(Ac, Ec, Wc1, b_in1, Q, KV);
    attn_kernel<<<1024, 256>>>(loop, Q, KV, ATTc);
    outln_mma  <<<128, 256, SMEM_OUT>>>(ATTc, Wo1, b_out1, face, ln1_g, ln1_b, X, Ac);

    // ---- layer 2 ----
    qkv_mma    <<<384, 256, SMEM_QKV>>>(Ac, Ec, Wc2, b_in2, Q, KV);
    attn_kernel<<<1024, 256>>>(loop, Q, KV, ATTc);
    outln_mma  <<<128, 256, SMEM_OUT>>>(ATTc, Wo2, b_out2, X, ln2_g, ln2_b,
                                        (float*)d_out, (half_t*)nullptr);
}

// round 6
// speedup vs baseline: 3.8784x; 1.3654x over previous
#include <cuda_runtime.h>
#include <cuda_fp16.h>
#include <cstdint>

typedef unsigned int u32;
typedef __half half_t;

#define EDIM    256
#define MAXLOOP 16

// ---------------------------------------------------------------------------
// Global scratch (no allocation allowed)
// ---------------------------------------------------------------------------
__device__ float  g_Q  [8192 * 256];
__device__ half_t g_KV [8192 * 512];       // fp16: K cols 0..255, V cols 256..511
__device__ float  g_X  [8192 * 256];
__device__ half_t g_Ac [8192 * 256];       // activations fp16 (face, then X)
__device__ half_t g_Ec [8192 * 256];       // edges fp16
__device__ half_t g_ATTc[8192 * 256];      // attention out fp16
__device__ half_t g_Wc1[768 * 256];        // weights fp16
__device__ half_t g_Wc2[768 * 256];
__device__ half_t g_Wo1[256 * 256];
__device__ half_t g_Wo2[256 * 256];

// ---------------------------------------------------------------------------
// Helpers (plain sm_80+ features only — harness lowers to compute_103 PTX)
// ---------------------------------------------------------------------------
__device__ __forceinline__ u32 smem_u32(const void* p) {
    u32 a; asm("{ .reg .u64 t; cvta.to.shared.u64 t, %1; cvt.u32.u64 %0, t; }"
               : "=r"(a) : "l"(p));
    return a;
}
__device__ __forceinline__ void cpa16(u32 d, const void* s) {
    asm volatile("cp.async.ca.shared.global [%0], [%1], 16;" :: "r"(d), "l"(s));
}
#define CP_COMMIT() asm volatile("cp.async.commit_group;" ::: "memory")
#define CP_WAIT(n)  asm volatile("cp.async.wait_group %0;" :: "n"(n) : "memory")
#define LDSM4(r0, r1, r2, r3, a) \
    asm volatile("ldmatrix.sync.aligned.m8n8.x4.shared.b16 {%0,%1,%2,%3}, [%4];" \
                 : "=r"(r0), "=r"(r1), "=r"(r2), "=r"(r3) : "r"(a))

__device__ __forceinline__ void mma_f16(float* d, const u32* a, const u32* b) {
    asm volatile("mma.sync.aligned.m16n8k16.row.col.f32.f16.f16.f32 "
                 "{%0,%1,%2,%3}, {%4,%5,%6,%7}, {%8,%9}, {%0,%1,%2,%3};"
                 : "+f"(d[0]), "+f"(d[1]), "+f"(d[2]), "+f"(d[3])
                 : "r"(a[0]), "r"(a[1]), "r"(a[2]), "r"(a[3]),
                   "r"(b[0]), "r"(b[1]));
}

__device__ __forceinline__ u32 h2u(__half2 h) { return *reinterpret_cast<u32*>(&h); }
__device__ __forceinline__ __half2 u2h(u32 u) { return *reinterpret_cast<__half2*>(&u); }

// round 8 fp32 -> 8 fp16 (uint4)
__device__ __forceinline__ uint4 round8h(float4 f0, float4 f1) {
    return make_uint4(h2u(__floats2half2_rn(f0.x, f0.y)),
                      h2u(__floats2half2_rn(f0.z, f0.w)),
                      h2u(__floats2half2_rn(f1.x, f1.y)),
                      h2u(__floats2half2_rn(f1.z, f1.w)));
}

// ---------------------------------------------------------------------------
// conv_all: face[8192], edge[8192], w1[768], o1[256], w2[768], o2[256]
// fp32 [rows][256] -> fp16 [rows][256], one launch (18432 rows, 2304 blocks)
// ---------------------------------------------------------------------------
__global__ void conv_all(const float* __restrict__ f, const float* __restrict__ e,
                         const float* __restrict__ w1, const float* __restrict__ o1,
                         const float* __restrict__ w2, const float* __restrict__ o2,
                         half_t* __restrict__ Ac, half_t* __restrict__ Ec,
                         half_t* __restrict__ W1, half_t* __restrict__ O1,
                         half_t* __restrict__ W2, half_t* __restrict__ O2)
{
    const int idx = blockIdx.x * 256 + threadIdx.x;
    int row = idx >> 5;
    const int c = (idx & 31) * 8;
    const float* src; half_t* dst;
    if      (row < 8192)  { src = f;  dst = Ac; }
    else if (row < 16384) { src = e;  dst = Ec; row -= 8192; }
    else if (row < 17152) { src = w1; dst = W1; row -= 16384; }
    else if (row < 17408) { src = o1; dst = O1; row -= 17152; }
    else if (row < 18176) { src = w2; dst = W2; row -= 17408; }
    else                  { src = o2; dst = O2; row -= 18176; }
    const float* s = src + (size_t)row * 256 + c;
    float4 f0 = *(const float4*)s, f1 = *(const float4*)(s + 4);
    *(uint4*)&dst[(size_t)row * 256 + c] = round8h(f0, f1);
}

// ---------------------------------------------------------------------------
// GEMM core: A [M][256] fp16, B [N][256] fp16, C = A*B^T (fp32 accum).
// K-chunk 64, double-buffered cp.async. smem chunk: A MBx144 | B NBx144.
// Warp tile 32x64, m16n8k16.
// ---------------------------------------------------------------------------
template<int MB, int NB, int NTH>
__device__ __forceinline__ void load_chunk(u32 sb, const half_t* __restrict__ A,
                                           const half_t* __restrict__ B, int m0, int kc)
{
    const int tid = threadIdx.x;
    constexpr u32 AREG = MB * 144u;
#pragma unroll
    for (int i = tid; i < MB * 8; i += NTH) {
        const int r = i >> 3, s = i & 7;
        cpa16(sb + r * 144 + s * 16,
              A + ((size_t)(m0 + r) << 8) + kc * 64 + s * 8);
    }
#pragma unroll
    for (int i = tid; i < NB * 8; i += NTH) {
        const int r = i >> 3, s = i & 7;
        cpa16(sb + AREG + r * 144 + s * 16,
              B + ((size_t)r << 8) + kc * 64 + s * 8);
    }
}

template<int MB, int NB>
__device__ __forceinline__ void mma_chunk(u32 sb, int wm, int wn, int lane,
                                          float c[2][8][4])
{
    constexpr u32 OFF_B = MB * 144u;
    const u32 arow  = lane & 15;
    const u32 ahalf = (lane >> 4) * 16;
#pragma unroll
    for (int ks = 0; ks < 4; ++ks) {
        const u32 kb = ks * 32 + ahalf;
        u32 ah[2][4];
#pragma unroll
        for (int t = 0; t < 2; ++t) {
            const u32 ad = sb + (wm * 32 + t * 16 + arow) * 144 + kb;
            LDSM4(ah[t][0], ah[t][1], ah[t][2], ah[t][3], ad);
        }
#pragma unroll
        for (int p = 0; p < 4; ++p) {
            const u32 bd = sb + OFF_B + (wn * 64 + p * 16 + arow) * 144 + kb;
            u32 m0r, m1r, m2r, m3r;
            LDSM4(m0r, m1r, m2r, m3r, bd);
            u32 b0[2] = { m0r, m2r }, b1[2] = { m1r, m3r };
#pragma unroll
            for (int t = 0; t < 2; ++t) {
                mma_f16(c[t][2 * p],     ah[t], b0);
                mma_f16(c[t][2 * p + 1], ah[t], b1);
            }
        }
    }
}

template<int MB, int NB, int NTH>
__device__ __forceinline__ void gemm_pipe(u32 sb, const half_t* __restrict__ A,
                                          const half_t* __restrict__ B, int m0,
                                          int wm, int wn, int lane, float c[2][8][4])
{
    constexpr u32 CHUNK = (MB + NB) * 144u;
    load_chunk<MB, NB, NTH>(sb, A, B, m0, 0);         CP_COMMIT();
    load_chunk<MB, NB, NTH>(sb + CHUNK, A, B, m0, 1); CP_COMMIT();
#pragma unroll
    for (int kc = 0; kc < 4; ++kc) {
        if (kc < 3) { CP_WAIT(1); } else { CP_WAIT(0); }
        __syncthreads();
        mma_chunk<MB, NB>(sb + (kc & 1) * CHUNK, wm, wn, lane, c);
        __syncthreads();
        if (kc < 2) {
            load_chunk<MB, NB, NTH>(sb + (kc & 1) * CHUNK, A, B, m0, kc + 2);
            CP_COMMIT();
        }
    }
}

// ---------------------------------------------------------------------------
// QKV GEMM: grid = 64 mtiles x 6 ntiles. ntile<2 -> Q fp32 (A=acts);
// ntile>=2 -> K/V fp16 (A=edges). CTA 128x128, 256 threads.
// ---------------------------------------------------------------------------
#define SMEM_QKV (2 * ((128 + 128) * 144))

__global__ __launch_bounds__(256, 2)
void qkv_mma(const half_t* __restrict__ Ain, const half_t* __restrict__ Ein,
             const half_t* __restrict__ W, const float* __restrict__ bias,
             float* __restrict__ Qo, half_t* __restrict__ KVo)
{
    extern __shared__ char smem[];
    const u32 sb = smem_u32(smem);
    const int mtile = blockIdx.x & 63, ntile = blockIdx.x >> 6;
    const int m0 = mtile * 128, n0 = ntile * 128;
    const half_t* A = (ntile < 2) ? Ain : Ein;
    const half_t* B = W + (size_t)n0 * 256;
    const int wid = threadIdx.x >> 5, lane = threadIdx.x & 31;
    const int wm = wid >> 1, wn = wid & 1;

    float c[2][8][4] = {};
    gemm_pipe<128, 128, 256>(sb, A, B, m0, wm, wn, lane, c);

    if (ntile < 2) {
#pragma unroll
        for (int t = 0; t < 2; ++t)
#pragma unroll
            for (int u = 0; u < 8; ++u) {
                const int row = m0 + wm * 32 + t * 16 + (lane >> 2);
                const int col = wn * 64 + u * 8 + (lane & 3) * 2;
                const float b0 = bias[n0 + col], b1 = bias[n0 + col + 1];
                float* p = Qo + (size_t)row * 256 + n0 + col;
                *(float2*)p              = make_float2(c[t][u][0] + b0, c[t][u][1] + b1);
                *(float2*)(p + 8 * 256)  = make_float2(c[t][u][2] + b0, c[t][u][3] + b1);
            }
    } else {
        const int cb = n0 - 256;
#pragma unroll
        for (int t = 0; t < 2; ++t)
#pragma unroll
            for (int u = 0; u < 8; ++u) {
                const int row = m0 + wm * 32 + t * 16 + (lane >> 2);
                const int col = wn * 64 + u * 8 + (lane & 3) * 2;
                const float b0 = bias[n0 + col], b1 = bias[n0 + col + 1];
                half_t* p = KVo + (size_t)row * 512 + cb + col;
                *(__half2*)p             = __floats2half2_rn(c[t][u][0] + b0, c[t][u][1] + b1);
                *(__half2*)(p + 8 * 512) = __floats2half2_rn(c[t][u][2] + b0, c[t][u][3] + b1);
            }
    }
}

// ---------------------------------------------------------------------------
// Out-proj GEMM + bias + residual + LayerNorm. CTA 64x256 (full row), grid 128.
// ---------------------------------------------------------------------------
#define SMEM_OUT (2 * ((64 + 256) * 144))

__global__ __launch_bounds__(256, 2)
void outln_mma(const half_t* __restrict__ A, const half_t* __restrict__ W,
               const float* __restrict__ bias, const float* __restrict__ resid,
               const float* __restrict__ gg, const float* __restrict__ bb,
               float* __restrict__ out, half_t* __restrict__ xc)
{
    extern __shared__ char smem[];
    const u32 sb = smem_u32(smem);
    const int m0 = blockIdx.x * 64;
    const int wid = threadIdx.x >> 5, lane = threadIdx.x & 31;
    const int wm = wid & 1, wn = wid >> 1;

    float c[2][8][4] = {};
    gemm_pipe<64, 256, 256>(sb, A, W, m0, wm, wn, lane, c);

    float* stash = (float*)smem;   // 64 rows x 264 floats
#pragma unroll
    for (int t = 0; t < 2; ++t)
#pragma unroll
        for (int u = 0; u < 8; ++u) {
            const int r = wm * 32 + t * 16 + (lane >> 2);
            const int col = wn * 64 + u * 8 + (lane & 3) * 2;
            const float b0 = bias[col], b1 = bias[col + 1];
            *(float2*)&stash[(size_t)r * 264 + col] =
                make_float2(c[t][u][0] + b0, c[t][u][1] + b1);
            *(float2*)&stash[(size_t)(r + 8) * 264 + col] =
                make_float2(c[t][u][2] + b0, c[t][u][3] + b1);
        }
    __syncthreads();

#pragma unroll
    for (int i = 0; i < 8; ++i) {
        const int r = wid * 8 + i;          // 0..63
        const int grow = m0 + r;
        const int c0 = lane * 8;
        float4 s0 = *(const float4*)&stash[(size_t)r * 264 + c0];
        float4 s1 = *(const float4*)&stash[(size_t)r * 264 + c0 + 4];
        const float* rp = resid + (size_t)grow * EDIM + c0;
        float4 r0 = *(const float4*)rp, r1 = *(const float4*)(rp + 4);
        float v[8] = { s0.x + r0.x, s0.y + r0.y, s0.z + r0.z, s0.w + r0.w,
                       s1.x + r1.x, s1.y + r1.y, s1.z + r1.z, s1.w + r1.w };
        float s = 0.f, ss = 0.f;
#pragma unroll
        for (int j = 0; j < 8; ++j) { s += v[j]; ss += v[j] * v[j]; }
#pragma unroll
        for (int d = 16; d; d >>= 1) {
            s  += __shfl_xor_sync(0xffffffffu, s,  d);
            ss += __shfl_xor_sync(0xffffffffu, ss, d);
        }
        const float m   = s * (1.f / 256.f);
        const float var = ss * (1.f / 256.f) - m * m;
        const float inv = rsqrtf(var + 1e-5f);

        float4 g0 = *(const float4*)(gg + c0), g1 = *(const float4*)(gg + c0 + 4);
        float4 b0 = *(const float4*)(bb + c0), b1 = *(const float4*)(bb + c0 + 4);
        float o[8];
        o[0] = (v[0] - m) * inv * g0.x + b0.x; o[1] = (v[1] - m) * inv * g0.y + b0.y;
        o[2] = (v[2] - m) * inv * g0.z + b0.z; o[3] = (v[3] - m) * inv * g0.w + b0.w;
        o[4] = (v[4] - m) * inv * g1.x + b1.x; o[5] = (v[5] - m) * inv * g1.y + b1.y;
        o[6] = (v[6] - m) * inv * g1.z + b1.z; o[7] = (v[7] - m) * inv * g1.w + b1.w;

        float* op = out + (size_t)grow * EDIM + c0;
        *(float4*)op       = make_float4(o[0], o[1], o[2], o[3]);
        *(float4*)(op + 4) = make_float4(o[4], o[5], o[6], o[7]);

        if (xc) {
            *(uint4*)&xc[(size_t)grow * 256 + c0] =
                round8h(make_float4(o[0], o[1], o[2], o[3]),
                        make_float4(o[4], o[5], o[6], o[7]));
        }
    }
}

// ---------------------------------------------------------------------------
// Attention: one warp per face; K/V fp16, Q fp32; emits fp16 output.
// ---------------------------------------------------------------------------
__global__ __launch_bounds__(256)
void attn_kernel(const int* __restrict__ loop, const float* __restrict__ Q,
                 const half_t* __restrict__ KV, half_t* __restrict__ attc)
{
    const int warp = threadIdx.x >> 5;
    const int lane = threadIdx.x & 31;
    const int face = (blockIdx.x << 3) + warp;

    __shared__ int sidx[8][16];
    if (lane < 16) sidx[warp][lane] = loop[face * MAXLOOP + lane];
    __syncwarp();

    bool v = false;
    if (lane < 16) {
        const int my = sidx[warp][lane];
        v = (my >= 0);
        for (int j = 0; v && j < lane; ++j)
            if (sidx[warp][j] == my) v = false;
    }
    const unsigned bal = __ballot_sync(0xffffffffu, v);

    const float scale = 0.08838834764831845f;  // 1/sqrt(128)
    const float* qp = Q + (size_t)face * EDIM + lane * 8;
    float4 q0 = *(const float4*)qp;
    float4 q1 = *(const float4*)(qp + 4);
    float q[8] = { q0.x * scale, q0.y * scale, q0.z * scale, q0.w * scale,
                   q1.x * scale, q1.y * scale, q1.z * scale, q1.w * scale };

    float myscore = -3e38f;
#pragma unroll
    for (int i = 0; i < 16; ++i) {
        if (!(bal & (1u << i))) continue;
        const int idx = sidx[warp][i];
        uint4 kr = *(const uint4*)(KV + (size_t)idx * 512 + lane * 8);
        float2 k0 = __half22float2(u2h(kr.x)), k1 = __half22float2(u2h(kr.y));
        float2 k2 = __half22float2(u2h(kr.z)), k3 = __half22float2(u2h(kr.w));
        float p = q[0] * k0.x + q[1] * k0.y + q[2] * k1.x + q[3] * k1.y
                + q[4] * k2.x + q[5] * k2.y + q[6] * k3.x + q[7] * k3.y;
        p += __shfl_xor_sync(0xffffffffu, p, 8);
        p += __shfl_xor_sync(0xffffffffu, p, 4);
        p += __shfl_xor_sync(0xffffffffu, p, 2);
        p += __shfl_xor_sync(0xffffffffu, p, 1);
        if ((lane & 15) == i) myscore = p;
    }

    const bool mv = (bal >> (lane & 15)) & 1u;
    float s = mv ? myscore : -3e38f;
    float mx = s;
#pragma unroll
    for (int d = 8; d; d >>= 1) mx = fmaxf(mx, __shfl_xor_sync(0xffffffffu, mx, d));
    float e = mv ? __expf(s - mx) : 0.f;
    float sum = e;
#pragma unroll
    for (int d = 8; d; d >>= 1) sum += __shfl_xor_sync(0xffffffffu, sum, d);
    const float w = e / sum;

    float a[8] = {};
    const int hb = lane & 16;
#pragma unroll
    for (int i = 0; i < 16; ++i) {
        if (!(bal & (1u << i))) continue;
        const int idx = sidx[warp][i];
        const float wi = __shfl_sync(0xffffffffu, w, hb | i);
        uint4 vr = *(const uint4*)(KV + (size_t)idx * 512 + 256 + lane * 8);
        float2 v0 = __half22float2(u2h(vr.x)), v1 = __half22float2(u2h(vr.y));
        float2 v2 = __half22float2(u2h(vr.z)), v3 = __half22float2(u2h(vr.w));
        a[0] = fmaf(wi, v0.x, a[0]); a[1] = fmaf(wi, v0.y, a[1]);
        a[2] = fmaf(wi, v1.x, a[2]); a[3] = fmaf(wi, v1.y, a[3]);
        a[4] = fmaf(wi, v2.x, a[4]); a[5] = fmaf(wi, v2.y, a[5]);
        a[6] = fmaf(wi, v3.x, a[6]); a[7] = fmaf(wi, v3.y, a[7]);
    }
    *(uint4*)&attc[(size_t)face * 256 + lane * 8] =
        round8h(make_float4(a[0], a[1], a[2], a[3]),
                make_float4(a[4], a[5], a[6], a[7]));
}

// ---------------------------------------------------------------------------
extern "C" void kernel_launch(void* const* d_in, const int* in_sizes, int n_in,
                              void* d_out, int out_size)
{
    const int*   loop  = (const int*)  d_in[0];
    const float* edge  = (const float*)d_in[2];
    const float* face  = (const float*)d_in[3];
    const float* w_in1  = (const float*)d_in[4];
    const float* b_in1  = (const float*)d_in[5];
    const float* w_out1 = (const float*)d_in[6];
    const float* b_out1 = (const float*)d_in[7];
    const float* ln1_g  = (const float*)d_in[8];
    const float* ln1_b  = (const float*)d_in[9];
    const float* w_in2  = (const float*)d_in[10];
    const float* b_in2  = (const float*)d_in[11];
    const float* w_out2 = (const float*)d_in[12];
    const float* b_out2 = (const float*)d_in[13];
    const float* ln2_g  = (const float*)d_in[14];
    const float* ln2_b  = (const float*)d_in[15];

    float *Q, *X;
    half_t *KV, *Ac, *Ec, *ATTc, *Wc1, *Wc2, *Wo1, *Wo2;
    cudaGetSymbolAddress((void**)&Q,    g_Q);
    cudaGetSymbolAddress((void**)&KV,   g_KV);
    cudaGetSymbolAddress((void**)&X,    g_X);
    cudaGetSymbolAddress((void**)&Ac,   g_Ac);
    cudaGetSymbolAddress((void**)&Ec,   g_Ec);
    cudaGetSymbolAddress((void**)&ATTc, g_ATTc);
    cudaGetSymbolAddress((void**)&Wc1,  g_Wc1);
    cudaGetSymbolAddress((void**)&Wc2,  g_Wc2);
    cudaGetSymbolAddress((void**)&Wo1,  g_Wo1);
    cudaGetSymbolAddress((void**)&Wo2,  g_Wo2);

    cudaFuncSetAttribute(qkv_mma,   cudaFuncAttributeMaxDynamicSharedMemorySize, SMEM_QKV);
    cudaFuncSetAttribute(outln_mma, cudaFuncAttributeMaxDynamicSharedMemorySize, SMEM_OUT);

    conv_all<<<2304, 256>>>(face, edge, w_in1, w_out1, w_in2, w_out2,
                            Ac, Ec, Wc1, Wo1, Wc2, Wo2);

    // ---- layer 1 ----
    qkv_mma    <<<384, 256, SMEM_QKV>>>(Ac, Ec, Wc1, b_in1, Q, KV);
    attn_kernel<<<1024, 256>>>(loop, Q, KV, ATTc);
    outln_mma  <<<128, 256, SMEM_OUT>>>(ATTc, Wo1, b_out1, face, ln1_g, ln1_b, X, Ac);

    // ---- layer 2 ----
    qkv_mma    <<<384, 256, SMEM_QKV>>>(Ac, Ec, Wc2, b_in2, Q, KV);
    attn_kernel<<<1024, 256>>>(loop, Q, KV, ATTc);
    outln_mma  <<<128, 256, SMEM_OUT>>>(ATTc, Wo2, b_out2, X, ln2_g, ln2_b,
                                        (float*)d_out, (half_t*)nullptr);
}